// round 14
// baseline (speedup 1.0000x reference)
#include <cuda_runtime.h>
#include <cuda_fp16.h>
#include <cstdint>

// Problem constants
#define VOCAB 32000
#define DMODEL 1024
#define NHEAD 16
#define HDIM 64
#define FFDIM 4096
#define NLAYER 4
#define SEQ 2048
#define BATCH 2
#define MTOK (BATCH * SEQ)      // 4096 token rows
#define HK (NHEAD * HDIM)       // 1024
#define QKVN 3072               // fused q|k|v output width

// ---------------------------------------------------------------------------
// Scratch (device globals; no allocations allowed)
// ---------------------------------------------------------------------------
__device__ float g_x[MTOK * DMODEL];                 // residual stream fp32
__device__ float g_qkvb[NLAYER * QKVN];              // fused qkv bias
__device__ __half g_qkvh[MTOK * QKVN];               // fused qkv fp16
__device__ __half g_xh[MTOK * DMODEL];               // activations fp16
__device__ __half g_ah[MTOK * HK];
__device__ __half g_fh[MTOK * FFDIM];
// fp16 weights, NATURAL [K,N] layout
__device__ __half g_wqkv[NLAYER * DMODEL * QKVN];
__device__ __half g_wo[NLAYER * HK * DMODEL];
__device__ __half g_w1[NLAYER * DMODEL * FFDIM];
__device__ __half g_w2[NLAYER * FFDIM * DMODEL];
__device__ __half g_wf[DMODEL * VOCAB];

// ---------------------------------------------------------------------------
// PTX helpers (all sm_80-era, arch-portable)
// ---------------------------------------------------------------------------
__device__ __forceinline__ uint32_t smem_u32(const void* p) {
    return (uint32_t)__cvta_generic_to_shared(p);
}
__device__ __forceinline__ void cp_async16(uint32_t dst, const void* src) {
    asm volatile("cp.async.cg.shared.global [%0], [%1], 16;\n" :: "r"(dst), "l"(src));
}
__device__ __forceinline__ void cp_commit() { asm volatile("cp.async.commit_group;\n" ::: "memory"); }
template<int N> __device__ __forceinline__ void cp_wait() {
    asm volatile("cp.async.wait_group %0;\n" :: "n"(N) : "memory");
}
__device__ __forceinline__ void ldsm_x4(uint32_t* r, uint32_t addr) {
    asm volatile("ldmatrix.sync.aligned.m8n8.x4.shared.b16 {%0,%1,%2,%3}, [%4];"
                 : "=r"(r[0]), "=r"(r[1]), "=r"(r[2]), "=r"(r[3]) : "r"(addr));
}
__device__ __forceinline__ void ldsm_x4_trans(uint32_t* r, uint32_t addr) {
    asm volatile("ldmatrix.sync.aligned.m8n8.x4.trans.shared.b16 {%0,%1,%2,%3}, [%4];"
                 : "=r"(r[0]), "=r"(r[1]), "=r"(r[2]), "=r"(r[3]) : "r"(addr));
}
__device__ __forceinline__ void mma_f16(float* c, const uint32_t* a, const uint32_t* b) {
    asm volatile(
        "mma.sync.aligned.m16n8k16.row.col.f32.f16.f16.f32 "
        "{%0,%1,%2,%3}, {%4,%5,%6,%7}, {%8,%9}, {%0,%1,%2,%3};"
        : "+f"(c[0]), "+f"(c[1]), "+f"(c[2]), "+f"(c[3])
        : "r"(a[0]), "r"(a[1]), "r"(a[2]), "r"(a[3]), "r"(b[0]), "r"(b[1]));
}
// fp16-accumulate variant: D/C are 2x .f16x2 regs
__device__ __forceinline__ void mma_f16acc(uint32_t* c, const uint32_t* a, const uint32_t* b) {
    asm volatile(
        "mma.sync.aligned.m16n8k16.row.col.f16.f16.f16.f16 "
        "{%0,%1}, {%2,%3,%4,%5}, {%6,%7}, {%0,%1};"
        : "+r"(c[0]), "+r"(c[1])
        : "r"(a[0]), "r"(a[1]), "r"(a[2]), "r"(a[3]), "r"(b[0]), "r"(b[1]));
}

// ---------------------------------------------------------------------------
// Flat weight convert: fp32 -> fp16, 8 elements per thread (16B store).
// ---------------------------------------------------------------------------
__global__ void wconv_flat(const float* __restrict__ W, __half* __restrict__ Wh,
                           long n8)
{
    long i = (long)blockIdx.x * blockDim.x + threadIdx.x;
    if (i >= n8) return;
    const float4* p = (const float4*)(W + i * 8);
    float4 a = p[0], b = p[1];
    __half2 h0 = __floats2half2_rn(a.x, a.y), h1 = __floats2half2_rn(a.z, a.w);
    __half2 h2 = __floats2half2_rn(b.x, b.y), h3 = __floats2half2_rn(b.z, b.w);
    uint4 o;
    o.x = *(uint32_t*)&h0; o.y = *(uint32_t*)&h1;
    o.z = *(uint32_t*)&h2; o.w = *(uint32_t*)&h3;
    *(uint4*)(Wh + i * 8) = o;
}

// Packed qkv convert: in rows of HK, out rows of QKVN at column offset coff.
__global__ void wconv_qkv(const float* __restrict__ W, __half* __restrict__ Wh,
                          int coff)
{
    long row = blockIdx.x;
    int t = threadIdx.x;               // 0..127
    const float4* p = (const float4*)(W + row * HK + t * 8);
    float4 a = p[0], b = p[1];
    __half2 h0 = __floats2half2_rn(a.x, a.y), h1 = __floats2half2_rn(a.z, a.w);
    __half2 h2 = __floats2half2_rn(b.x, b.y), h3 = __floats2half2_rn(b.z, b.w);
    uint4 o;
    o.x = *(uint32_t*)&h0; o.y = *(uint32_t*)&h1;
    o.z = *(uint32_t*)&h2; o.w = *(uint32_t*)&h3;
    *(uint4*)(Wh + row * QKVN + coff + t * 8) = o;
}

// ---------------------------------------------------------------------------
// Embedding: x = emb[token] + pos ; also writes fp16
// ---------------------------------------------------------------------------
__global__ void embed_kernel(const int* __restrict__ tokens,
                             const float* __restrict__ emb,
                             const float* __restrict__ pos,
                             float* __restrict__ x,
                             __half* __restrict__ xh)
{
    int row = blockIdx.x;
    int s = row & (SEQ - 1);
    int t = tokens[row];
    const float4* e = (const float4*)(emb + (long)t * DMODEL);
    const float4* p = (const float4*)(pos + (long)s * DMODEL);
    for (int d = threadIdx.x; d < DMODEL / 4; d += blockDim.x) {
        float4 a = e[d], b = p[d];
        a.x += b.x; a.y += b.y; a.z += b.z; a.w += b.w;
        long o = (long)row * DMODEL + d * 4;
        *(float4*)&x[o] = a;
        __half2 h01, h23;
        h01.x = __float2half_rn(a.x); h01.y = __float2half_rn(a.y);
        h23.x = __float2half_rn(a.z); h23.y = __float2half_rn(a.w);
        *(__half2*)&xh[o] = h01; *(__half2*)&xh[o + 2] = h23;
    }
}

// qkv bias concat
__global__ void bias_concat_kernel(const float* __restrict__ bq, const float* __restrict__ bk,
                                   const float* __restrict__ bv, float* __restrict__ out)
{
    int i = blockIdx.x * blockDim.x + threadIdx.x;
    if (i >= NLAYER * QKVN) return;
    int l = i / QKVN, c = i - l * QKVN;
    float v = (c < 1024) ? bq[l * 1024 + c]
            : (c < 2048) ? bk[l * 1024 + c - 1024]
                         : bv[l * 1024 + c - 2048];
    out[i] = v;
}

// ---------------------------------------------------------------------------
// HMMA GEMM: C[M,N] = A[M,K] @ B  (A fp16 [M,K]; B fp16 [K,N] natural)
// CTA 128x128, BK=64, 8 warps (2x4), warp tile 64x32, mma.sync m16n8k16.
// fp16 accumulation within each BK=64 chunk, fp32 spill per chunk.
// 3-stage cp.async pipeline; 1 CTA/SM (extra regs for dual accumulators).
// ---------------------------------------------------------------------------
#define ASTRIDE 144                 // A smem row stride bytes (64 halves + pad)
#define ATILE_B 18432               // [128][72] halves
#define BSTRIDE 272                 // B smem row stride bytes (128 halves + pad)
#define BTILE_B 17408               // [64][136] halves
#define STAGE_B (ATILE_B + BTILE_B)       // 35840
#define GEMM_SMEM (3 * STAGE_B)           // 107520

template<bool RELU, bool RESID, bool WF32, bool WH16>
__global__ __launch_bounds__(256, 1)
void hmma_gemm(const __half* __restrict__ A, const __half* __restrict__ B,
               const float* __restrict__ bias, const float* __restrict__ resid,
               float* __restrict__ Cf, __half* __restrict__ Ch,
               int N, int K)
{
    extern __shared__ char smem[];
    uint32_t sbase = smem_u32(smem);

    int tid = threadIdx.x;
    int lane = tid & 31;
    int wid = tid >> 5;
    int wm = wid & 1;
    int wn = wid >> 1;
    int row0 = blockIdx.x * 128;
    int ncol0 = blockIdx.y * 128;
    int nk = K >> 6;

    float c[4][4][4];
#pragma unroll
    for (int i = 0; i < 4; i++)
#pragma unroll
        for (int j = 0; j < 4; j++)
#pragma unroll
            for (int k = 0; k < 4; k++) c[i][j][k] = 0.f;

    auto load_stage = [&](int chunk, int buf) {
        uint32_t sb = sbase + buf * STAGE_B;
        int kc = chunk << 6;
#pragma unroll 4
        for (int i = tid; i < 1024; i += 256) {
            int r = i >> 3, sg = i & 7;
            cp_async16(sb + (uint32_t)(r * ASTRIDE + sg * 16),
                       A + (long)(row0 + r) * K + kc + sg * 8);
        }
#pragma unroll 4
        for (int i = tid; i < 1024; i += 256) {
            int r = i >> 4, cc = i & 15;
            cp_async16(sb + ATILE_B + (uint32_t)(r * BSTRIDE + cc * 16),
                       B + (long)(kc + r) * N + ncol0 + cc * 8);
        }
        cp_commit();
    };

    load_stage(0, 0);
    load_stage(1, 1);

    int arow = (lane & 7) + ((lane >> 3) & 1) * 8;
    int akk = ((lane >> 4) & 1) * 8;
    int bt = lane >> 3, br = lane & 7;
    int brow_off = (bt & 1) * 8 + br;
    int bcol_off = (bt >> 1) * 8;

    int buf = 0;
    for (int ch = 0; ch < nk; ch++) {
        if (ch + 1 < nk) cp_wait<1>(); else cp_wait<0>();
        __syncthreads();
        if (ch + 2 < nk) {
            int nb = buf + 2; if (nb >= 3) nb -= 3;
            load_stage(ch + 2, nb);
        }

        uint32_t sb = sbase + buf * STAGE_B;

        // fp16 chunk accumulators, zeroed per chunk
        uint32_t c16[4][4][2];
#pragma unroll
        for (int mi = 0; mi < 4; mi++)
#pragma unroll
            for (int ni = 0; ni < 4; ni++) {
                c16[mi][ni][0] = 0u; c16[mi][ni][1] = 0u;
            }

#pragma unroll
        for (int ks = 0; ks < 4; ks++) {
            int k0 = ks * 16;
            uint32_t a_r[4][4], b_r[4][2];
#pragma unroll
            for (int mi = 0; mi < 4; mi++) {
                uint32_t ad = sb + (uint32_t)((wm * 64 + mi * 16 + arow) * ASTRIDE
                                              + (k0 + akk) * 2);
                ldsm_x4(a_r[mi], ad);
            }
#pragma unroll
            for (int p = 0; p < 2; p++) {
                uint32_t bd = sb + ATILE_B
                            + (uint32_t)((k0 + brow_off) * BSTRIDE
                                         + (wn * 32 + p * 16 + bcol_off) * 2);
                uint32_t r[4];
                ldsm_x4_trans(r, bd);
                b_r[2 * p][0] = r[0]; b_r[2 * p][1] = r[1];
                b_r[2 * p + 1][0] = r[2]; b_r[2 * p + 1][1] = r[3];
            }
#pragma unroll
            for (int mi = 0; mi < 4; mi++)
#pragma unroll
                for (int ni = 0; ni < 4; ni++)
                    mma_f16acc(c16[mi][ni], a_r[mi], b_r[ni]);
        }

        // spill fp16 chunk accumulators into fp32
#pragma unroll
        for (int mi = 0; mi < 4; mi++)
#pragma unroll
            for (int ni = 0; ni < 4; ni++) {
                float2 f0 = __half22float2(*(__half2*)&c16[mi][ni][0]);
                float2 f1 = __half22float2(*(__half2*)&c16[mi][ni][1]);
                c[mi][ni][0] += f0.x; c[mi][ni][1] += f0.y;
                c[mi][ni][2] += f1.x; c[mi][ni][3] += f1.y;
            }

        if (++buf == 3) buf = 0;
    }

    int rbase = row0 + wm * 64 + (lane >> 2);
    int cbase = ncol0 + wn * 32 + (lane & 3) * 2;
#pragma unroll
    for (int mi = 0; mi < 4; mi++) {
#pragma unroll
        for (int ni = 0; ni < 4; ni++) {
            int gc = cbase + ni * 8;
            float b0 = __ldg(&bias[gc]), b1 = __ldg(&bias[gc + 1]);
#pragma unroll
            for (int half_ = 0; half_ < 2; half_++) {
                long gr = rbase + mi * 16 + half_ * 8;
                float v0 = c[mi][ni][half_ * 2 + 0] + b0;
                float v1 = c[mi][ni][half_ * 2 + 1] + b1;
                if (RELU) { v0 = fmaxf(v0, 0.f); v1 = fmaxf(v1, 0.f); }
                if (RESID) {
                    float2 rr = *(const float2*)&resid[gr * N + gc];
                    v0 += rr.x; v1 += rr.y;
                }
                if (WF32) {
                    float2 o; o.x = v0; o.y = v1;
                    *(float2*)&Cf[gr * N + gc] = o;
                }
                if (WH16) {
                    __half2 hh;
                    hh.x = __float2half_rn(v0); hh.y = __float2half_rn(v1);
                    *(__half2*)&Ch[gr * N + gc] = hh;
                }
            }
        }
    }
}

// ---------------------------------------------------------------------------
// HMMA flash attention. CTA = 128 q-rows x one head. 8 warps x 16 rows.
// (unchanged from round 11 — protect the win)
// ---------------------------------------------------------------------------
#define FSTR 144   // smem row stride bytes (64 halves + 8 pad)
#define FQ_B (128 * FSTR)          // 18432
#define FK_B (64 * FSTR)           // 9216
#define FLASH_SMEM2 (FQ_B + 2 * FK_B)  // 36864

__global__ __launch_bounds__(256, 2)
void flash_attn_hmma(const __half* __restrict__ QKV, __half* __restrict__ Ao)
{
    extern __shared__ char sm8[];
    uint32_t sq = smem_u32(sm8);
    uint32_t sk = sq + FQ_B;
    uint32_t sv = sk + FK_B;

    int qt = gridDim.x - 1 - blockIdx.x;
    int bh = blockIdx.y;
    int b = bh >> 4, h = bh & 15;
    int tid = threadIdx.x, lane = tid & 31, wid = tid >> 5;

    const __half* Qg = QKV + (long)b * SEQ * QKVN + h * HDIM;
    const __half* Kg = Qg + 1024;
    const __half* Vg = Qg + 2048;

    for (int i = tid; i < 1024; i += 256) {
        int r = i >> 3, sg = i & 7;
        cp_async16(sq + (uint32_t)(r * FSTR + sg * 16),
                   Qg + (long)(qt * 128 + r) * QKVN + sg * 8);
    }
    cp_commit();

    int arow = (lane & 7) + ((lane >> 3) & 1) * 8;
    int akk = ((lane >> 4) & 1) * 8;
    int bt = lane >> 3, br = lane & 7;
    int brow_off = (bt & 1) * 8 + br;
    int bcol_off = (bt >> 1) * 8;

    cp_wait<0>();
    __syncthreads();

    uint32_t a_q[4][4];
#pragma unroll
    for (int ks = 0; ks < 4; ks++)
        ldsm_x4(a_q[ks], sq + (uint32_t)((wid * 16 + arow) * FSTR + (ks * 16 + akk) * 2));

    float o[8][4];
#pragma unroll
    for (int i = 0; i < 8; i++)
#pragma unroll
        for (int j = 0; j < 4; j++) o[i][j] = 0.f;
    float m_[2] = {-1e30f, -1e30f}, l_[2] = {0.f, 0.f};

    int rloc = wid * 16 + (lane >> 2);
    int r0g = qt * 128 + rloc;
    int njt = 2 * qt + 2;

    for (int jt = 0; jt < njt; jt++) {
        __syncthreads();
        for (int i = tid; i < 512; i += 256) {
            int r = i >> 3, sg = i & 7;
            long g = (long)(jt * 64 + r) * QKVN + sg * 8;
            cp_async16(sk + (uint32_t)(r * FSTR + sg * 16), Kg + g);
            cp_async16(sv + (uint32_t)(r * FSTR + sg * 16), Vg + g);
        }
        cp_commit();
        cp_wait<0>();
        __syncthreads();

        float cs[8][4];
#pragma unroll
        for (int i = 0; i < 8; i++)
#pragma unroll
            for (int j = 0; j < 4; j++) cs[i][j] = 0.f;

#pragma unroll
        for (int ks = 0; ks < 4; ks++) {
            uint32_t b_r[8][2];
#pragma unroll
            for (int p = 0; p < 4; p++) {
                uint32_t r[4];
                ldsm_x4(r, sk + (uint32_t)((p * 16 + arow) * FSTR + (ks * 16 + akk) * 2));
                b_r[2 * p][0] = r[0]; b_r[2 * p + 1][0] = r[1];
                b_r[2 * p][1] = r[2]; b_r[2 * p + 1][1] = r[3];
            }
#pragma unroll
            for (int ni = 0; ni < 8; ni++)
                mma_f16(cs[ni], a_q[ks], b_r[ni]);
        }

        bool need_mask = (jt * 64 + 63) > (qt * 128 + wid * 16);
        if (need_mask) {
#pragma unroll
            for (int ni = 0; ni < 8; ni++) {
                int k0c = jt * 64 + ni * 8 + (lane & 3) * 2;
#pragma unroll
                for (int hf = 0; hf < 2; hf++) {
                    int qrow = r0g + hf * 8;
                    float v0 = cs[ni][hf * 2 + 0] * 0.125f;
                    float v1 = cs[ni][hf * 2 + 1] * 0.125f;
                    cs[ni][hf * 2 + 0] = (k0c > qrow) ? -1e30f : v0;
                    cs[ni][hf * 2 + 1] = (k0c + 1 > qrow) ? -1e30f : v1;
                }
            }
        } else {
#pragma unroll
            for (int ni = 0; ni < 8; ni++)
#pragma unroll
                for (int j = 0; j < 4; j++) cs[ni][j] *= 0.125f;
        }

#pragma unroll
        for (int hf = 0; hf < 2; hf++) {
            float mx = m_[hf];
#pragma unroll
            for (int ni = 0; ni < 8; ni++)
                mx = fmaxf(mx, fmaxf(cs[ni][hf * 2], cs[ni][hf * 2 + 1]));
            mx = fmaxf(mx, __shfl_xor_sync(0xffffffffu, mx, 1));
            mx = fmaxf(mx, __shfl_xor_sync(0xffffffffu, mx, 2));
            float corr = __expf(m_[hf] - mx);
            float rsum = 0.f;
#pragma unroll
            for (int ni = 0; ni < 8; ni++) {
                float p0 = __expf(cs[ni][hf * 2 + 0] - mx);
                float p1 = __expf(cs[ni][hf * 2 + 1] - mx);
                cs[ni][hf * 2 + 0] = p0;
                cs[ni][hf * 2 + 1] = p1;
                rsum += p0 + p1;
            }
            rsum += __shfl_xor_sync(0xffffffffu, rsum, 1);
            rsum += __shfl_xor_sync(0xffffffffu, rsum, 2);
            l_[hf] = l_[hf] * corr + rsum;
            m_[hf] = mx;
#pragma unroll
            for (int ni = 0; ni < 8; ni++) {
                o[ni][hf * 2 + 0] *= corr;
                o[ni][hf * 2 + 1] *= corr;
            }
        }

#pragma unroll
        for (int ks2 = 0; ks2 < 4; ks2++) {
            uint32_t a_p[4];
            {
                __half2 t0 = __floats2half2_rn(cs[2 * ks2][0], cs[2 * ks2][1]);
                __half2 t1 = __floats2half2_rn(cs[2 * ks2][2], cs[2 * ks2][3]);
                __half2 t2 = __floats2half2_rn(cs[2 * ks2 + 1][0], cs[2 * ks2 + 1][1]);
                __half2 t3 = __floats2half2_rn(cs[2 * ks2 + 1][2], cs[2 * ks2 + 1][3]);
                a_p[0] = *(uint32_t*)&t0; a_p[1] = *(uint32_t*)&t1;
                a_p[2] = *(uint32_t*)&t2; a_p[3] = *(uint32_t*)&t3;
            }
            uint32_t b_v[8][2];
#pragma unroll
            for (int p = 0; p < 4; p++) {
                uint32_t r[4];
                ldsm_x4_trans(r, sv + (uint32_t)((ks2 * 16 + brow_off) * FSTR
                                                 + (p * 16 + bcol_off) * 2));
                b_v[2 * p][0] = r[0]; b_v[2 * p][1] = r[1];
                b_v[2 * p + 1][0] = r[2]; b_v[2 * p + 1][1] = r[3];
            }
#pragma unroll
            for (int ni = 0; ni < 8; ni++)
                mma_f16(o[ni], a_p, b_v[ni]);
        }
    }

#pragma unroll
    for (int hf = 0; hf < 2; hf++) {
        float inv = 1.0f / l_[hf];
        long row = (long)(b * SEQ + r0g + hf * 8);
#pragma unroll
        for (int ni = 0; ni < 8; ni++) {
            __half2 hv = __floats2half2_rn(o[ni][hf * 2 + 0] * inv,
                                           o[ni][hf * 2 + 1] * inv);
            *(__half2*)&Ao[row * HK + h * HDIM + ni * 8 + (lane & 3) * 2] = hv;
        }
    }
}

// ---------------------------------------------------------------------------
// Launch
// ---------------------------------------------------------------------------
extern "C" void kernel_launch(void* const* d_in, const int* in_sizes, int n_in,
                              void* d_out, int out_size)
{
    const int*   tokens = (const int*)  d_in[0];
    const float* emb    = (const float*)d_in[1];
    const float* pos    = (const float*)d_in[2];
    const float* Wq     = (const float*)d_in[3];
    const float* bq     = (const float*)d_in[4];
    const float* Wk     = (const float*)d_in[5];
    const float* bk     = (const float*)d_in[6];
    const float* Wv     = (const float*)d_in[7];
    const float* bv     = (const float*)d_in[8];
    const float* Wo     = (const float*)d_in[9];
    const float* bo     = (const float*)d_in[10];
    const float* W1     = (const float*)d_in[11];
    const float* b1     = (const float*)d_in[12];
    const float* W2     = (const float*)d_in[13];
    const float* b2     = (const float*)d_in[14];
    const float* Wf     = (const float*)d_in[15];
    const float* bf     = (const float*)d_in[16];
    float* out = (float*)d_out;

    float *x, *qkvb;
    __half *qkvh, *xh, *ah, *fh;
    __half *wqkv, *wo, *w1, *w2, *wf;
    cudaGetSymbolAddress((void**)&x, g_x);
    cudaGetSymbolAddress((void**)&qkvb, g_qkvb);
    cudaGetSymbolAddress((void**)&qkvh, g_qkvh);
    cudaGetSymbolAddress((void**)&xh, g_xh);
    cudaGetSymbolAddress((void**)&ah, g_ah);
    cudaGetSymbolAddress((void**)&fh, g_fh);
    cudaGetSymbolAddress((void**)&wqkv, g_wqkv);
    cudaGetSymbolAddress((void**)&wo, g_wo);
    cudaGetSymbolAddress((void**)&w1, g_w1);
    cudaGetSymbolAddress((void**)&w2, g_w2);
    cudaGetSymbolAddress((void**)&wf, g_wf);

    static bool attr_set = false;
    if (!attr_set) {
        cudaFuncSetAttribute(flash_attn_hmma,
                             cudaFuncAttributeMaxDynamicSharedMemorySize, FLASH_SMEM2);
        cudaFuncSetAttribute(hmma_gemm<false, false, true, false>,
                             cudaFuncAttributeMaxDynamicSharedMemorySize, GEMM_SMEM);
        cudaFuncSetAttribute(hmma_gemm<false, false, false, true>,
                             cudaFuncAttributeMaxDynamicSharedMemorySize, GEMM_SMEM);
        cudaFuncSetAttribute(hmma_gemm<false, true, true, true>,
                             cudaFuncAttributeMaxDynamicSharedMemorySize, GEMM_SMEM);
        cudaFuncSetAttribute(hmma_gemm<true, false, false, true>,
                             cudaFuncAttributeMaxDynamicSharedMemorySize, GEMM_SMEM);
        attr_set = true;
    }

    // ---- weight convert: 8 launches total (all layers fused per tensor) ----
    wconv_qkv<<<NLAYER * DMODEL, 128>>>(Wq, wqkv, 0);
    wconv_qkv<<<NLAYER * DMODEL, 128>>>(Wk, wqkv, 1024);
    wconv_qkv<<<NLAYER * DMODEL, 128>>>(Wv, wqkv, 2048);
    {
        long n8;
        n8 = (long)NLAYER * HK * DMODEL / 8;
        wconv_flat<<<(unsigned)((n8 + 255) / 256), 256>>>(Wo, wo, n8);
        n8 = (long)NLAYER * DMODEL * FFDIM / 8;
        wconv_flat<<<(unsigned)((n8 + 255) / 256), 256>>>(W1, w1, n8);
        wconv_flat<<<(unsigned)((n8 + 255) / 256), 256>>>(W2, w2, n8);
        n8 = (long)DMODEL * VOCAB / 8;
        wconv_flat<<<(unsigned)((n8 + 255) / 256), 256>>>(Wf, wf, n8);
    }
    bias_concat_kernel<<<(NLAYER * QKVN + 255) / 256, 256>>>(bq, bk, bv, qkvb);

    // ---- forward ----
    embed_kernel<<<MTOK, 256>>>(tokens, emb, pos, x, xh);

    dim3 gQKV(MTOK / 128, QKVN / 128);
    dim3 gProj(MTOK / 128, DMODEL / 128);
    dim3 gFF1(MTOK / 128, FFDIM / 128);
    dim3 gLogits(MTOK / 128, VOCAB / 128);
    dim3 gAttn(SEQ / 128, BATCH * NHEAD);   // 16 x 32

    for (int l = 0; l < NLAYER; l++) {
        // qkv = x @ Wqkv + b  (fp16 out)
        hmma_gemm<false, false, false, true><<<gQKV, 256, GEMM_SMEM>>>(
            xh, wqkv + (long)l * DMODEL * QKVN, qkvb + (long)l * QKVN, nullptr,
            nullptr, qkvh, QKVN, DMODEL);

        flash_attn_hmma<<<gAttn, 256, FLASH_SMEM2>>>(qkvh, ah);

        // x = x + a @ Wo + bo  (fp32 + fp16 out)
        hmma_gemm<false, true, true, true><<<gProj, 256, GEMM_SMEM>>>(
            ah, wo + (long)l * HK * DMODEL,
            bo + (long)l * DMODEL, x, x, xh, DMODEL, HK);

        // f = relu(x @ W1 + b1)  (fp16 only)
        hmma_gemm<true, false, false, true><<<gFF1, 256, GEMM_SMEM>>>(
            xh, w1 + (long)l * DMODEL * FFDIM,
            b1 + (long)l * FFDIM, nullptr, nullptr, fh, FFDIM, DMODEL);

        // x = x + f @ W2 + b2
        hmma_gemm<false, true, true, true><<<gProj, 256, GEMM_SMEM>>>(
            fh, w2 + (long)l * FFDIM * DMODEL,
            b2 + (long)l * DMODEL, x, x, xh, DMODEL, FFDIM);
    }

    // logits = x @ Wf + bf
    hmma_gemm<false, false, true, false><<<gLogits, 256, GEMM_SMEM>>>(
        xh, wf, bf, nullptr, out, nullptr, VOCAB, DMODEL);
}

// round 15
// speedup vs baseline: 1.2911x; 1.2911x over previous
#include <cuda_runtime.h>
#include <cuda_fp16.h>
#include <cstdint>

// Problem constants
#define VOCAB 32000
#define DMODEL 1024
#define NHEAD 16
#define HDIM 64
#define FFDIM 4096
#define NLAYER 4
#define SEQ 2048
#define BATCH 2
#define MTOK (BATCH * SEQ)      // 4096 token rows
#define HK (NHEAD * HDIM)       // 1024
#define QKVN 3072               // fused q|k|v output width

// ---------------------------------------------------------------------------
// Scratch (device globals; no allocations allowed)
// ---------------------------------------------------------------------------
__device__ float g_x[MTOK * DMODEL];                 // residual stream fp32
__device__ float g_qkvb[NLAYER * QKVN];              // fused qkv bias
__device__ __half g_qkvh[MTOK * QKVN];               // fused qkv fp16
__device__ __half g_xh[MTOK * DMODEL];               // activations fp16
__device__ __half g_ah[MTOK * HK];
__device__ __half g_fh[MTOK * FFDIM];
// fp16 weights, NATURAL [K,N] layout
__device__ __half g_wqkv[NLAYER * DMODEL * QKVN];
__device__ __half g_wo[NLAYER * HK * DMODEL];
__device__ __half g_w1[NLAYER * DMODEL * FFDIM];
__device__ __half g_w2[NLAYER * FFDIM * DMODEL];
__device__ __half g_wf[DMODEL * VOCAB];

// ---------------------------------------------------------------------------
// PTX helpers (all sm_80-era, arch-portable)
// ---------------------------------------------------------------------------
__device__ __forceinline__ uint32_t smem_u32(const void* p) {
    return (uint32_t)__cvta_generic_to_shared(p);
}
__device__ __forceinline__ void cp_async16(uint32_t dst, const void* src) {
    asm volatile("cp.async.cg.shared.global [%0], [%1], 16;\n" :: "r"(dst), "l"(src));
}
__device__ __forceinline__ void cp_commit() { asm volatile("cp.async.commit_group;\n" ::: "memory"); }
template<int N> __device__ __forceinline__ void cp_wait() {
    asm volatile("cp.async.wait_group %0;\n" :: "n"(N) : "memory");
}
__device__ __forceinline__ void ldsm_x4(uint32_t* r, uint32_t addr) {
    asm volatile("ldmatrix.sync.aligned.m8n8.x4.shared.b16 {%0,%1,%2,%3}, [%4];"
                 : "=r"(r[0]), "=r"(r[1]), "=r"(r[2]), "=r"(r[3]) : "r"(addr));
}
__device__ __forceinline__ void ldsm_x4_trans(uint32_t* r, uint32_t addr) {
    asm volatile("ldmatrix.sync.aligned.m8n8.x4.trans.shared.b16 {%0,%1,%2,%3}, [%4];"
                 : "=r"(r[0]), "=r"(r[1]), "=r"(r[2]), "=r"(r[3]) : "r"(addr));
}
__device__ __forceinline__ void mma_f16(float* c, const uint32_t* a, const uint32_t* b) {
    asm volatile(
        "mma.sync.aligned.m16n8k16.row.col.f32.f16.f16.f32 "
        "{%0,%1,%2,%3}, {%4,%5,%6,%7}, {%8,%9}, {%0,%1,%2,%3};"
        : "+f"(c[0]), "+f"(c[1]), "+f"(c[2]), "+f"(c[3])
        : "r"(a[0]), "r"(a[1]), "r"(a[2]), "r"(a[3]), "r"(b[0]), "r"(b[1]));
}

// ---------------------------------------------------------------------------
// Flat weight convert: fp32 -> fp16, 16 elements per thread (2x 16B stores).
// ---------------------------------------------------------------------------
__global__ void wconv_flat(const float* __restrict__ W, __half* __restrict__ Wh,
                           long n16)
{
    long i = (long)blockIdx.x * blockDim.x + threadIdx.x;
    if (i >= n16) return;
    const float4* p = (const float4*)(W + i * 16);
    float4 a = p[0], b = p[1], cc = p[2], d = p[3];
    __half2 h0 = __floats2half2_rn(a.x, a.y), h1 = __floats2half2_rn(a.z, a.w);
    __half2 h2 = __floats2half2_rn(b.x, b.y), h3 = __floats2half2_rn(b.z, b.w);
    __half2 h4 = __floats2half2_rn(cc.x, cc.y), h5 = __floats2half2_rn(cc.z, cc.w);
    __half2 h6 = __floats2half2_rn(d.x, d.y), h7 = __floats2half2_rn(d.z, d.w);
    uint4 o0, o1;
    o0.x = *(uint32_t*)&h0; o0.y = *(uint32_t*)&h1;
    o0.z = *(uint32_t*)&h2; o0.w = *(uint32_t*)&h3;
    o1.x = *(uint32_t*)&h4; o1.y = *(uint32_t*)&h5;
    o1.z = *(uint32_t*)&h6; o1.w = *(uint32_t*)&h7;
    uint4* q = (uint4*)(Wh + i * 16);
    q[0] = o0; q[1] = o1;
}

// Packed qkv convert: in rows of HK, out rows of QKVN at column offset coff.
// grid.x = NLAYER*DMODEL rows, 64 threads x 16 elems.
__global__ void wconv_qkv(const float* __restrict__ W, __half* __restrict__ Wh,
                          int coff)
{
    long row = blockIdx.x;
    int t = threadIdx.x;               // 0..63
    const float4* p = (const float4*)(W + row * HK + t * 16);
    float4 a = p[0], b = p[1], cc = p[2], d = p[3];
    __half2 h0 = __floats2half2_rn(a.x, a.y), h1 = __floats2half2_rn(a.z, a.w);
    __half2 h2 = __floats2half2_rn(b.x, b.y), h3 = __floats2half2_rn(b.z, b.w);
    __half2 h4 = __floats2half2_rn(cc.x, cc.y), h5 = __floats2half2_rn(cc.z, cc.w);
    __half2 h6 = __floats2half2_rn(d.x, d.y), h7 = __floats2half2_rn(d.z, d.w);
    uint4 o0, o1;
    o0.x = *(uint32_t*)&h0; o0.y = *(uint32_t*)&h1;
    o0.z = *(uint32_t*)&h2; o0.w = *(uint32_t*)&h3;
    o1.x = *(uint32_t*)&h4; o1.y = *(uint32_t*)&h5;
    o1.z = *(uint32_t*)&h6; o1.w = *(uint32_t*)&h7;
    uint4* q = (uint4*)(Wh + row * QKVN + coff + t * 16);
    q[0] = o0; q[1] = o1;
}

// ---------------------------------------------------------------------------
// Embedding: x = emb[token] + pos ; also writes fp16
// ---------------------------------------------------------------------------
__global__ void embed_kernel(const int* __restrict__ tokens,
                             const float* __restrict__ emb,
                             const float* __restrict__ pos,
                             float* __restrict__ x,
                             __half* __restrict__ xh)
{
    int row = blockIdx.x;
    int s = row & (SEQ - 1);
    int t = tokens[row];
    const float4* e = (const float4*)(emb + (long)t * DMODEL);
    const float4* p = (const float4*)(pos + (long)s * DMODEL);
    for (int d = threadIdx.x; d < DMODEL / 4; d += blockDim.x) {
        float4 a = e[d], b = p[d];
        a.x += b.x; a.y += b.y; a.z += b.z; a.w += b.w;
        long o = (long)row * DMODEL + d * 4;
        *(float4*)&x[o] = a;
        __half2 h01, h23;
        h01.x = __float2half_rn(a.x); h01.y = __float2half_rn(a.y);
        h23.x = __float2half_rn(a.z); h23.y = __float2half_rn(a.w);
        *(__half2*)&xh[o] = h01; *(__half2*)&xh[o + 2] = h23;
    }
}

// qkv bias concat
__global__ void bias_concat_kernel(const float* __restrict__ bq, const float* __restrict__ bk,
                                   const float* __restrict__ bv, float* __restrict__ out)
{
    int i = blockIdx.x * blockDim.x + threadIdx.x;
    if (i >= NLAYER * QKVN) return;
    int l = i / QKVN, c = i - l * QKVN;
    float v = (c < 1024) ? bq[l * 1024 + c]
            : (c < 2048) ? bk[l * 1024 + c - 1024]
                         : bv[l * 1024 + c - 2048];
    out[i] = v;
}

// ---------------------------------------------------------------------------
// HMMA GEMM: C[M,N] = A[M,K] @ B  (A fp16 [M,K]; B fp16 [K,N] natural)
// CTA 128x128, BK=64, 8 warps (2x4), warp tile 64x32, mma.sync m16n8k16.
// fp32 accumulation; 3-stage cp.async pipeline; 2 CTAs/SM.  (R13 config)
// ---------------------------------------------------------------------------
#define ASTRIDE 144                 // A smem row stride bytes (64 halves + pad)
#define ATILE_B 18432               // [128][72] halves
#define BSTRIDE 272                 // B smem row stride bytes (128 halves + pad)
#define BTILE_B 17408               // [64][136] halves
#define STAGE_B (ATILE_B + BTILE_B)       // 35840
#define GEMM_SMEM (3 * STAGE_B)           // 107520

template<bool RELU, bool RESID, bool WF32, bool WH16>
__global__ __launch_bounds__(256, 2)
void hmma_gemm(const __half* __restrict__ A, const __half* __restrict__ B,
               const float* __restrict__ bias, const float* __restrict__ resid,
               float* __restrict__ Cf, __half* __restrict__ Ch,
               int N, int K)
{
    extern __shared__ char smem[];
    uint32_t sbase = smem_u32(smem);

    int tid = threadIdx.x;
    int lane = tid & 31;
    int wid = tid >> 5;
    int wm = wid & 1;
    int wn = wid >> 1;
    int row0 = blockIdx.x * 128;
    int ncol0 = blockIdx.y * 128;
    int nk = K >> 6;

    float c[4][4][4];
#pragma unroll
    for (int i = 0; i < 4; i++)
#pragma unroll
        for (int j = 0; j < 4; j++)
#pragma unroll
            for (int k = 0; k < 4; k++) c[i][j][k] = 0.f;

    auto load_stage = [&](int chunk, int buf) {
        uint32_t sb = sbase + buf * STAGE_B;
        int kc = chunk << 6;
#pragma unroll 4
        for (int i = tid; i < 1024; i += 256) {
            int r = i >> 3, sg = i & 7;
            cp_async16(sb + (uint32_t)(r * ASTRIDE + sg * 16),
                       A + (long)(row0 + r) * K + kc + sg * 8);
        }
#pragma unroll 4
        for (int i = tid; i < 1024; i += 256) {
            int r = i >> 4, cc = i & 15;
            cp_async16(sb + ATILE_B + (uint32_t)(r * BSTRIDE + cc * 16),
                       B + (long)(kc + r) * N + ncol0 + cc * 8);
        }
        cp_commit();
    };

    load_stage(0, 0);
    load_stage(1, 1);

    int arow = (lane & 7) + ((lane >> 3) & 1) * 8;
    int akk = ((lane >> 4) & 1) * 8;
    int bt = lane >> 3, br = lane & 7;
    int brow_off = (bt & 1) * 8 + br;
    int bcol_off = (bt >> 1) * 8;

    int buf = 0;
    for (int ch = 0; ch < nk; ch++) {
        if (ch + 1 < nk) cp_wait<1>(); else cp_wait<0>();
        __syncthreads();
        if (ch + 2 < nk) {
            int nb = buf + 2; if (nb >= 3) nb -= 3;
            load_stage(ch + 2, nb);
        }

        uint32_t sb = sbase + buf * STAGE_B;
#pragma unroll
        for (int ks = 0; ks < 4; ks++) {
            int k0 = ks * 16;
            uint32_t a_r[4][4], b_r[4][2];
#pragma unroll
            for (int mi = 0; mi < 4; mi++) {
                uint32_t ad = sb + (uint32_t)((wm * 64 + mi * 16 + arow) * ASTRIDE
                                              + (k0 + akk) * 2);
                ldsm_x4(a_r[mi], ad);
            }
#pragma unroll
            for (int p = 0; p < 2; p++) {
                uint32_t bd = sb + ATILE_B
                            + (uint32_t)((k0 + brow_off) * BSTRIDE
                                         + (wn * 32 + p * 16 + bcol_off) * 2);
                uint32_t r[4];
                ldsm_x4_trans(r, bd);
                b_r[2 * p][0] = r[0]; b_r[2 * p][1] = r[1];
                b_r[2 * p + 1][0] = r[2]; b_r[2 * p + 1][1] = r[3];
            }
#pragma unroll
            for (int mi = 0; mi < 4; mi++)
#pragma unroll
                for (int ni = 0; ni < 4; ni++)
                    mma_f16(c[mi][ni], a_r[mi], b_r[ni]);
        }
        if (++buf == 3) buf = 0;
    }

    int rbase = row0 + wm * 64 + (lane >> 2);
    int cbase = ncol0 + wn * 32 + (lane & 3) * 2;
#pragma unroll
    for (int mi = 0; mi < 4; mi++) {
#pragma unroll
        for (int ni = 0; ni < 4; ni++) {
            int gc = cbase + ni * 8;
            float b0 = __ldg(&bias[gc]), b1 = __ldg(&bias[gc + 1]);
#pragma unroll
            for (int half_ = 0; half_ < 2; half_++) {
                long gr = rbase + mi * 16 + half_ * 8;
                float v0 = c[mi][ni][half_ * 2 + 0] + b0;
                float v1 = c[mi][ni][half_ * 2 + 1] + b1;
                if (RELU) { v0 = fmaxf(v0, 0.f); v1 = fmaxf(v1, 0.f); }
                if (RESID) {
                    float2 rr = *(const float2*)&resid[gr * N + gc];
                    v0 += rr.x; v1 += rr.y;
                }
                if (WF32) {
                    float2 o; o.x = v0; o.y = v1;
                    *(float2*)&Cf[gr * N + gc] = o;
                }
                if (WH16) {
                    __half2 hh;
                    hh.x = __float2half_rn(v0); hh.y = __float2half_rn(v1);
                    *(__half2*)&Ch[gr * N + gc] = hh;
                }
            }
        }
    }
}

// ---------------------------------------------------------------------------
// HMMA flash attention. CTA = 128 q-rows x one head. 8 warps x 16 rows.
// K/V double-buffered: prefetch tile jt+1 overlaps compute of tile jt.
// ---------------------------------------------------------------------------
#define FSTR 144   // smem row stride bytes (64 halves + 8 pad)
#define FQ_B (128 * FSTR)              // 18432
#define FKV_B (2 * 64 * FSTR)          // 18432 (K + V, one buffer)
#define FLASH_SMEM2 (FQ_B + 2 * FKV_B) // 55296

__global__ __launch_bounds__(256, 2)
void flash_attn_hmma(const __half* __restrict__ QKV, __half* __restrict__ Ao)
{
    extern __shared__ char sm8[];
    uint32_t sq = smem_u32(sm8);
    uint32_t skv0 = sq + FQ_B;          // buffer 0: K then V

    int qt = gridDim.x - 1 - blockIdx.x;
    int bh = blockIdx.y;
    int b = bh >> 4, h = bh & 15;
    int tid = threadIdx.x, lane = tid & 31, wid = tid >> 5;

    const __half* Qg = QKV + (long)b * SEQ * QKVN + h * HDIM;
    const __half* Kg = Qg + 1024;
    const __half* Vg = Qg + 2048;

    // Load Q tile
    for (int i = tid; i < 1024; i += 256) {
        int r = i >> 3, sg = i & 7;
        cp_async16(sq + (uint32_t)(r * FSTR + sg * 16),
                   Qg + (long)(qt * 128 + r) * QKVN + sg * 8);
    }
    cp_commit();

    auto load_kv = [&](int jt, int kbuf) {
        uint32_t sk = skv0 + kbuf * FKV_B;
        uint32_t sv = sk + 64 * FSTR;
        for (int i = tid; i < 512; i += 256) {
            int r = i >> 3, sg = i & 7;
            long g = (long)(jt * 64 + r) * QKVN + sg * 8;
            cp_async16(sk + (uint32_t)(r * FSTR + sg * 16), Kg + g);
            cp_async16(sv + (uint32_t)(r * FSTR + sg * 16), Vg + g);
        }
        cp_commit();
    };

    int arow = (lane & 7) + ((lane >> 3) & 1) * 8;
    int akk = ((lane >> 4) & 1) * 8;
    int bt = lane >> 3, br = lane & 7;
    int brow_off = (bt & 1) * 8 + br;
    int bcol_off = (bt >> 1) * 8;

    // first K/V load (Q load still in same queue: wait all below)
    load_kv(0, 0);
    cp_wait<0>();
    __syncthreads();

    uint32_t a_q[4][4];
#pragma unroll
    for (int ks = 0; ks < 4; ks++)
        ldsm_x4(a_q[ks], sq + (uint32_t)((wid * 16 + arow) * FSTR + (ks * 16 + akk) * 2));

    float o[8][4];
#pragma unroll
    for (int i = 0; i < 8; i++)
#pragma unroll
        for (int j = 0; j < 4; j++) o[i][j] = 0.f;
    float m_[2] = {-1e30f, -1e30f}, l_[2] = {0.f, 0.f};

    int rloc = wid * 16 + (lane >> 2);
    int r0g = qt * 128 + rloc;
    int njt = 2 * qt + 2;

    for (int jt = 0; jt < njt; jt++) {
        int kbuf = jt & 1;
        if (jt > 0) {                 // wait for this tile's prefetch
            cp_wait<0>();
            __syncthreads();          // also: all warps done with buf kbuf
        }
        if (jt + 1 < njt) load_kv(jt + 1, kbuf ^ 1);

        uint32_t sk = skv0 + kbuf * FKV_B;
        uint32_t sv = sk + 64 * FSTR;

        // ---- S = Q @ K^T ----
        float cs[8][4];
#pragma unroll
        for (int i = 0; i < 8; i++)
#pragma unroll
            for (int j = 0; j < 4; j++) cs[i][j] = 0.f;

#pragma unroll
        for (int ks = 0; ks < 4; ks++) {
            uint32_t b_r[8][2];
#pragma unroll
            for (int p = 0; p < 4; p++) {
                uint32_t r[4];
                ldsm_x4(r, sk + (uint32_t)((p * 16 + arow) * FSTR + (ks * 16 + akk) * 2));
                b_r[2 * p][0] = r[0]; b_r[2 * p + 1][0] = r[1];
                b_r[2 * p][1] = r[2]; b_r[2 * p + 1][1] = r[3];
            }
#pragma unroll
            for (int ni = 0; ni < 8; ni++)
                mma_f16(cs[ni], a_q[ks], b_r[ni]);
        }

        bool need_mask = (jt * 64 + 63) > (qt * 128 + wid * 16);
        if (need_mask) {
#pragma unroll
            for (int ni = 0; ni < 8; ni++) {
                int k0c = jt * 64 + ni * 8 + (lane & 3) * 2;
#pragma unroll
                for (int hf = 0; hf < 2; hf++) {
                    int qrow = r0g + hf * 8;
                    float v0 = cs[ni][hf * 2 + 0] * 0.125f;
                    float v1 = cs[ni][hf * 2 + 1] * 0.125f;
                    cs[ni][hf * 2 + 0] = (k0c > qrow) ? -1e30f : v0;
                    cs[ni][hf * 2 + 1] = (k0c + 1 > qrow) ? -1e30f : v1;
                }
            }
        } else {
#pragma unroll
            for (int ni = 0; ni < 8; ni++)
#pragma unroll
                for (int j = 0; j < 4; j++) cs[ni][j] *= 0.125f;
        }

#pragma unroll
        for (int hf = 0; hf < 2; hf++) {
            float mx = m_[hf];
#pragma unroll
            for (int ni = 0; ni < 8; ni++)
                mx = fmaxf(mx, fmaxf(cs[ni][hf * 2], cs[ni][hf * 2 + 1]));
            mx = fmaxf(mx, __shfl_xor_sync(0xffffffffu, mx, 1));
            mx = fmaxf(mx, __shfl_xor_sync(0xffffffffu, mx, 2));
            float corr = __expf(m_[hf] - mx);
            float rsum = 0.f;
#pragma unroll
            for (int ni = 0; ni < 8; ni++) {
                float p0 = __expf(cs[ni][hf * 2 + 0] - mx);
                float p1 = __expf(cs[ni][hf * 2 + 1] - mx);
                cs[ni][hf * 2 + 0] = p0;
                cs[ni][hf * 2 + 1] = p1;
                rsum += p0 + p1;
            }
            rsum += __shfl_xor_sync(0xffffffffu, rsum, 1);
            rsum += __shfl_xor_sync(0xffffffffu, rsum, 2);
            l_[hf] = l_[hf] * corr + rsum;
            m_[hf] = mx;
#pragma unroll
            for (int ni = 0; ni < 8; ni++) {
                o[ni][hf * 2 + 0] *= corr;
                o[ni][hf * 2 + 1] *= corr;
            }
        }

#pragma unroll
        for (int ks2 = 0; ks2 < 4; ks2++) {
            uint32_t a_p[4];
            {
                __half2 t0 = __floats2half2_rn(cs[2 * ks2][0], cs[2 * ks2][1]);
                __half2 t1 = __floats2half2_rn(cs[2 * ks2][2], cs[2 * ks2][3]);
                __half2 t2 = __floats2half2_rn(cs[2 * ks2 + 1][0], cs[2 * ks2 + 1][1]);
                __half2 t3 = __floats2half2_rn(cs[2 * ks2 + 1][2], cs[2 * ks2 + 1][3]);
                a_p[0] = *(uint32_t*)&t0; a_p[1] = *(uint32_t*)&t1;
                a_p[2] = *(uint32_t*)&t2; a_p[3] = *(uint32_t*)&t3;
            }
            uint32_t b_v[8][2];
#pragma unroll
            for (int p = 0; p < 4; p++) {
                uint32_t r[4];
                ldsm_x4_trans(r, sv + (uint32_t)((ks2 * 16 + brow_off) * FSTR
                                                 + (p * 16 + bcol_off) * 2));
                b_v[2 * p][0] = r[0]; b_v[2 * p][1] = r[1];
                b_v[2 * p + 1][0] = r[2]; b_v[2 * p + 1][1] = r[3];
            }
#pragma unroll
            for (int ni = 0; ni < 8; ni++)
                mma_f16(o[ni], a_p, b_v[ni]);
        }
        __syncthreads();   // all warps done with buf kbuf before next prefetch wait
    }

#pragma unroll
    for (int hf = 0; hf < 2; hf++) {
        float inv = 1.0f / l_[hf];
        long row = (long)(b * SEQ + r0g + hf * 8);
#pragma unroll
        for (int ni = 0; ni < 8; ni++) {
            __half2 hv = __floats2half2_rn(o[ni][hf * 2 + 0] * inv,
                                           o[ni][hf * 2 + 1] * inv);
            *(__half2*)&Ao[row * HK + h * HDIM + ni * 8 + (lane & 3) * 2] = hv;
        }
    }
}

// ---------------------------------------------------------------------------
// Launch
// ---------------------------------------------------------------------------
extern "C" void kernel_launch(void* const* d_in, const int* in_sizes, int n_in,
                              void* d_out, int out_size)
{
    const int*   tokens = (const int*)  d_in[0];
    const float* emb    = (const float*)d_in[1];
    const float* pos    = (const float*)d_in[2];
    const float* Wq     = (const float*)d_in[3];
    const float* bq     = (const float*)d_in[4];
    const float* Wk     = (const float*)d_in[5];
    const float* bk     = (const float*)d_in[6];
    const float* Wv     = (const float*)d_in[7];
    const float* bv     = (const float*)d_in[8];
    const float* Wo     = (const float*)d_in[9];
    const float* bo     = (const float*)d_in[10];
    const float* W1     = (const float*)d_in[11];
    const float* b1     = (const float*)d_in[12];
    const float* W2     = (const float*)d_in[13];
    const float* b2     = (const float*)d_in[14];
    const float* Wf     = (const float*)d_in[15];
    const float* bf     = (const float*)d_in[16];
    float* out = (float*)d_out;

    float *x, *qkvb;
    __half *qkvh, *xh, *ah, *fh;
    __half *wqkv, *wo, *w1, *w2, *wf;
    cudaGetSymbolAddress((void**)&x, g_x);
    cudaGetSymbolAddress((void**)&qkvb, g_qkvb);
    cudaGetSymbolAddress((void**)&qkvh, g_qkvh);
    cudaGetSymbolAddress((void**)&xh, g_xh);
    cudaGetSymbolAddress((void**)&ah, g_ah);
    cudaGetSymbolAddress((void**)&fh, g_fh);
    cudaGetSymbolAddress((void**)&wqkv, g_wqkv);
    cudaGetSymbolAddress((void**)&wo, g_wo);
    cudaGetSymbolAddress((void**)&w1, g_w1);
    cudaGetSymbolAddress((void**)&w2, g_w2);
    cudaGetSymbolAddress((void**)&wf, g_wf);

    static bool attr_set = false;
    if (!attr_set) {
        cudaFuncSetAttribute(flash_attn_hmma,
                             cudaFuncAttributeMaxDynamicSharedMemorySize, FLASH_SMEM2);
        cudaFuncSetAttribute(hmma_gemm<false, false, true, false>,
                             cudaFuncAttributeMaxDynamicSharedMemorySize, GEMM_SMEM);
        cudaFuncSetAttribute(hmma_gemm<false, false, false, true>,
                             cudaFuncAttributeMaxDynamicSharedMemorySize, GEMM_SMEM);
        cudaFuncSetAttribute(hmma_gemm<false, true, true, true>,
                             cudaFuncAttributeMaxDynamicSharedMemorySize, GEMM_SMEM);
        cudaFuncSetAttribute(hmma_gemm<true, false, false, true>,
                             cudaFuncAttributeMaxDynamicSharedMemorySize, GEMM_SMEM);
        attr_set = true;
    }

    // ---- weight convert: 8 launches total (all layers fused per tensor) ----
    wconv_qkv<<<NLAYER * DMODEL, 64>>>(Wq, wqkv, 0);
    wconv_qkv<<<NLAYER * DMODEL, 64>>>(Wk, wqkv, 1024);
    wconv_qkv<<<NLAYER * DMODEL, 64>>>(Wv, wqkv, 2048);
    {
        long n16;
        n16 = (long)NLAYER * HK * DMODEL / 16;
        wconv_flat<<<(unsigned)((n16 + 255) / 256), 256>>>(Wo, wo, n16);
        n16 = (long)NLAYER * DMODEL * FFDIM / 16;
        wconv_flat<<<(unsigned)((n16 + 255) / 256), 256>>>(W1, w1, n16);
        wconv_flat<<<(unsigned)((n16 + 255) / 256), 256>>>(W2, w2, n16);
        n16 = (long)DMODEL * VOCAB / 16;
        wconv_flat<<<(unsigned)((n16 + 255) / 256), 256>>>(Wf, wf, n16);
    }
    bias_concat_kernel<<<(NLAYER * QKVN + 255) / 256, 256>>>(bq, bk, bv, qkvb);

    // ---- forward ----
    embed_kernel<<<MTOK, 256>>>(tokens, emb, pos, x, xh);

    dim3 gQKV(MTOK / 128, QKVN / 128);
    dim3 gProj(MTOK / 128, DMODEL / 128);
    dim3 gFF1(MTOK / 128, FFDIM / 128);
    dim3 gLogits(MTOK / 128, VOCAB / 128);
    dim3 gAttn(SEQ / 128, BATCH * NHEAD);   // 16 x 32

    for (int l = 0; l < NLAYER; l++) {
        // qkv = x @ Wqkv + b  (fp16 out)
        hmma_gemm<false, false, false, true><<<gQKV, 256, GEMM_SMEM>>>(
            xh, wqkv + (long)l * DMODEL * QKVN, qkvb + (long)l * QKVN, nullptr,
            nullptr, qkvh, QKVN, DMODEL);

        flash_attn_hmma<<<gAttn, 256, FLASH_SMEM2>>>(qkvh, ah);

        // x = x + a @ Wo + bo  (fp32 + fp16 out)
        hmma_gemm<false, true, true, true><<<gProj, 256, GEMM_SMEM>>>(
            ah, wo + (long)l * HK * DMODEL,
            bo + (long)l * DMODEL, x, x, xh, DMODEL, HK);

        // f = relu(x @ W1 + b1)  (fp16 only)
        hmma_gemm<true, false, false, true><<<gFF1, 256, GEMM_SMEM>>>(
            xh, w1 + (long)l * DMODEL * FFDIM,
            b1 + (long)l * FFDIM, nullptr, nullptr, fh, FFDIM, DMODEL);

        // x = x + f @ W2 + b2
        hmma_gemm<false, true, true, true><<<gProj, 256, GEMM_SMEM>>>(
            fh, w2 + (long)l * FFDIM * DMODEL,
            b2 + (long)l * DMODEL, x, x, xh, DMODEL, FFDIM);
    }

    // logits = x @ Wf + bf
    hmma_gemm<false, false, true, false><<<gLogits, 256, GEMM_SMEM>>>(
        xh, wf, bf, nullptr, out, nullptr, VOCAB, DMODEL);
}

// round 16
// speedup vs baseline: 1.3038x; 1.0098x over previous
#include <cuda_runtime.h>
#include <cuda_fp16.h>
#include <cstdint>

// Problem constants
#define VOCAB 32000
#define DMODEL 1024
#define NHEAD 16
#define HDIM 64
#define FFDIM 4096
#define NLAYER 4
#define SEQ 2048
#define BATCH 2
#define MTOK (BATCH * SEQ)      // 4096 token rows
#define HK (NHEAD * HDIM)       // 1024
#define QKVN 3072               // fused q|k|v output width

// ---------------------------------------------------------------------------
// Scratch (device globals; no allocations allowed)
// ---------------------------------------------------------------------------
__device__ float g_x[MTOK * DMODEL];                 // residual stream fp32
__device__ float g_qkvb[NLAYER * QKVN];              // fused qkv bias
__device__ __half g_qkvh[MTOK * QKVN];               // fused qkv fp16
__device__ __half g_xh[MTOK * DMODEL];               // activations fp16
__device__ __half g_ah[MTOK * HK];
__device__ __half g_fh[MTOK * FFDIM];
// fp16 weights, NATURAL [K,N] layout
__device__ __half g_wqkv[NLAYER * DMODEL * QKVN];
__device__ __half g_wo[NLAYER * HK * DMODEL];
__device__ __half g_w1[NLAYER * DMODEL * FFDIM];
__device__ __half g_w2[NLAYER * FFDIM * DMODEL];
__device__ __half g_wf[DMODEL * VOCAB];

// ---------------------------------------------------------------------------
// PTX helpers (all sm_80-era, arch-portable)
// ---------------------------------------------------------------------------
__device__ __forceinline__ uint32_t smem_u32(const void* p) {
    return (uint32_t)__cvta_generic_to_shared(p);
}
__device__ __forceinline__ void cp_async16(uint32_t dst, const void* src) {
    asm volatile("cp.async.cg.shared.global [%0], [%1], 16;\n" :: "r"(dst), "l"(src));
}
__device__ __forceinline__ void cp_commit() { asm volatile("cp.async.commit_group;\n" ::: "memory"); }
template<int N> __device__ __forceinline__ void cp_wait() {
    asm volatile("cp.async.wait_group %0;\n" :: "n"(N) : "memory");
}
__device__ __forceinline__ void ldsm_x4(uint32_t* r, uint32_t addr) {
    asm volatile("ldmatrix.sync.aligned.m8n8.x4.shared.b16 {%0,%1,%2,%3}, [%4];"
                 : "=r"(r[0]), "=r"(r[1]), "=r"(r[2]), "=r"(r[3]) : "r"(addr));
}
__device__ __forceinline__ void ldsm_x4_trans(uint32_t* r, uint32_t addr) {
    asm volatile("ldmatrix.sync.aligned.m8n8.x4.trans.shared.b16 {%0,%1,%2,%3}, [%4];"
                 : "=r"(r[0]), "=r"(r[1]), "=r"(r[2]), "=r"(r[3]) : "r"(addr));
}
__device__ __forceinline__ void mma_f16(float* c, const uint32_t* a, const uint32_t* b) {
    asm volatile(
        "mma.sync.aligned.m16n8k16.row.col.f32.f16.f16.f32 "
        "{%0,%1,%2,%3}, {%4,%5,%6,%7}, {%8,%9}, {%0,%1,%2,%3};"
        : "+f"(c[0]), "+f"(c[1]), "+f"(c[2]), "+f"(c[3])
        : "r"(a[0]), "r"(a[1]), "r"(a[2]), "r"(a[3]), "r"(b[0]), "r"(b[1]));
}

// ---------------------------------------------------------------------------
// Flat weight convert: fp32 -> fp16, 16 elements per thread (2x 16B stores).
// ---------------------------------------------------------------------------
__global__ void wconv_flat(const float* __restrict__ W, __half* __restrict__ Wh,
                           long n16)
{
    long i = (long)blockIdx.x * blockDim.x + threadIdx.x;
    if (i >= n16) return;
    const float4* p = (const float4*)(W + i * 16);
    float4 a = p[0], b = p[1], cc = p[2], d = p[3];
    __half2 h0 = __floats2half2_rn(a.x, a.y), h1 = __floats2half2_rn(a.z, a.w);
    __half2 h2 = __floats2half2_rn(b.x, b.y), h3 = __floats2half2_rn(b.z, b.w);
    __half2 h4 = __floats2half2_rn(cc.x, cc.y), h5 = __floats2half2_rn(cc.z, cc.w);
    __half2 h6 = __floats2half2_rn(d.x, d.y), h7 = __floats2half2_rn(d.z, d.w);
    uint4 o0, o1;
    o0.x = *(uint32_t*)&h0; o0.y = *(uint32_t*)&h1;
    o0.z = *(uint32_t*)&h2; o0.w = *(uint32_t*)&h3;
    o1.x = *(uint32_t*)&h4; o1.y = *(uint32_t*)&h5;
    o1.z = *(uint32_t*)&h6; o1.w = *(uint32_t*)&h7;
    uint4* q = (uint4*)(Wh + i * 16);
    q[0] = o0; q[1] = o1;
}

// Packed qkv convert: in rows of HK, out rows of QKVN at column offset coff.
__global__ void wconv_qkv(const float* __restrict__ W, __half* __restrict__ Wh,
                          int coff)
{
    long row = blockIdx.x;
    int t = threadIdx.x;               // 0..63
    const float4* p = (const float4*)(W + row * HK + t * 16);
    float4 a = p[0], b = p[1], cc = p[2], d = p[3];
    __half2 h0 = __floats2half2_rn(a.x, a.y), h1 = __floats2half2_rn(a.z, a.w);
    __half2 h2 = __floats2half2_rn(b.x, b.y), h3 = __floats2half2_rn(b.z, b.w);
    __half2 h4 = __floats2half2_rn(cc.x, cc.y), h5 = __floats2half2_rn(cc.z, cc.w);
    __half2 h6 = __floats2half2_rn(d.x, d.y), h7 = __floats2half2_rn(d.z, d.w);
    uint4 o0, o1;
    o0.x = *(uint32_t*)&h0; o0.y = *(uint32_t*)&h1;
    o0.z = *(uint32_t*)&h2; o0.w = *(uint32_t*)&h3;
    o1.x = *(uint32_t*)&h4; o1.y = *(uint32_t*)&h5;
    o1.z = *(uint32_t*)&h6; o1.w = *(uint32_t*)&h7;
    uint4* q = (uint4*)(Wh + row * QKVN + coff + t * 16);
    q[0] = o0; q[1] = o1;
}

// ---------------------------------------------------------------------------
// Embedding: x = emb[token] + pos ; also writes fp16
// ---------------------------------------------------------------------------
__global__ void embed_kernel(const int* __restrict__ tokens,
                             const float* __restrict__ emb,
                             const float* __restrict__ pos,
                             float* __restrict__ x,
                             __half* __restrict__ xh)
{
    int row = blockIdx.x;
    int s = row & (SEQ - 1);
    int t = tokens[row];
    const float4* e = (const float4*)(emb + (long)t * DMODEL);
    const float4* p = (const float4*)(pos + (long)s * DMODEL);
    for (int d = threadIdx.x; d < DMODEL / 4; d += blockDim.x) {
        float4 a = e[d], b = p[d];
        a.x += b.x; a.y += b.y; a.z += b.z; a.w += b.w;
        long o = (long)row * DMODEL + d * 4;
        *(float4*)&x[o] = a;
        __half2 h01, h23;
        h01.x = __float2half_rn(a.x); h01.y = __float2half_rn(a.y);
        h23.x = __float2half_rn(a.z); h23.y = __float2half_rn(a.w);
        *(__half2*)&xh[o] = h01; *(__half2*)&xh[o + 2] = h23;
    }
}

// qkv bias concat
__global__ void bias_concat_kernel(const float* __restrict__ bq, const float* __restrict__ bk,
                                   const float* __restrict__ bv, float* __restrict__ out)
{
    int i = blockIdx.x * blockDim.x + threadIdx.x;
    if (i >= NLAYER * QKVN) return;
    int l = i / QKVN, c = i - l * QKVN;
    float v = (c < 1024) ? bq[l * 1024 + c]
            : (c < 2048) ? bk[l * 1024 + c - 1024]
                         : bv[l * 1024 + c - 2048];
    out[i] = v;
}

// ---------------------------------------------------------------------------
// HMMA GEMM: C[M,N] = A[M,K] @ B  (A fp16 [M,K]; B fp16 [K,N] natural)
// CTA 128x128, BK=64, 8 warps (2x4), warp tile 64x32, mma.sync m16n8k16.
// fp32 accumulation; 3-stage cp.async pipeline; 2 CTAs/SM.
// ---------------------------------------------------------------------------
#define ASTRIDE 144                 // A smem row stride bytes (64 halves + pad)
#define ATILE_B 18432               // [128][72] halves
#define BSTRIDE 272                 // B smem row stride bytes (128 halves + pad)
#define BTILE_B 17408               // [64][136] halves
#define STAGE_B (ATILE_B + BTILE_B)       // 35840
#define GEMM_SMEM (3 * STAGE_B)           // 107520

template<bool RELU, bool RESID, bool WF32, bool WH16>
__global__ __launch_bounds__(256, 2)
void hmma_gemm(const __half* __restrict__ A, const __half* __restrict__ B,
               const float* __restrict__ bias, const float* __restrict__ resid,
               float* __restrict__ Cf, __half* __restrict__ Ch,
               int N, int K)
{
    extern __shared__ char smem[];
    uint32_t sbase = smem_u32(smem);

    int tid = threadIdx.x;
    int lane = tid & 31;
    int wid = tid >> 5;
    int wm = wid & 1;
    int wn = wid >> 1;
    int row0 = blockIdx.x * 128;
    int ncol0 = blockIdx.y * 128;
    int nk = K >> 6;

    float c[4][4][4];
#pragma unroll
    for (int i = 0; i < 4; i++)
#pragma unroll
        for (int j = 0; j < 4; j++)
#pragma unroll
            for (int k = 0; k < 4; k++) c[i][j][k] = 0.f;

    auto load_stage = [&](int chunk, int buf) {
        uint32_t sb = sbase + buf * STAGE_B;
        int kc = chunk << 6;
#pragma unroll 4
        for (int i = tid; i < 1024; i += 256) {
            int r = i >> 3, sg = i & 7;
            cp_async16(sb + (uint32_t)(r * ASTRIDE + sg * 16),
                       A + (long)(row0 + r) * K + kc + sg * 8);
        }
#pragma unroll 4
        for (int i = tid; i < 1024; i += 256) {
            int r = i >> 4, cc = i & 15;
            cp_async16(sb + ATILE_B + (uint32_t)(r * BSTRIDE + cc * 16),
                       B + (long)(kc + r) * N + ncol0 + cc * 8);
        }
        cp_commit();
    };

    load_stage(0, 0);
    load_stage(1, 1);

    int arow = (lane & 7) + ((lane >> 3) & 1) * 8;
    int akk = ((lane >> 4) & 1) * 8;
    int bt = lane >> 3, br = lane & 7;
    int brow_off = (bt & 1) * 8 + br;
    int bcol_off = (bt >> 1) * 8;

    int buf = 0;
    for (int ch = 0; ch < nk; ch++) {
        if (ch + 1 < nk) cp_wait<1>(); else cp_wait<0>();
        __syncthreads();
        if (ch + 2 < nk) {
            int nb = buf + 2; if (nb >= 3) nb -= 3;
            load_stage(ch + 2, nb);
        }

        uint32_t sb = sbase + buf * STAGE_B;
#pragma unroll
        for (int ks = 0; ks < 4; ks++) {
            int k0 = ks * 16;
            uint32_t a_r[4][4], b_r[4][2];
#pragma unroll
            for (int mi = 0; mi < 4; mi++) {
                uint32_t ad = sb + (uint32_t)((wm * 64 + mi * 16 + arow) * ASTRIDE
                                              + (k0 + akk) * 2);
                ldsm_x4(a_r[mi], ad);
            }
#pragma unroll
            for (int p = 0; p < 2; p++) {
                uint32_t bd = sb + ATILE_B
                            + (uint32_t)((k0 + brow_off) * BSTRIDE
                                         + (wn * 32 + p * 16 + bcol_off) * 2);
                uint32_t r[4];
                ldsm_x4_trans(r, bd);
                b_r[2 * p][0] = r[0]; b_r[2 * p][1] = r[1];
                b_r[2 * p + 1][0] = r[2]; b_r[2 * p + 1][1] = r[3];
            }
#pragma unroll
            for (int mi = 0; mi < 4; mi++)
#pragma unroll
                for (int ni = 0; ni < 4; ni++)
                    mma_f16(c[mi][ni], a_r[mi], b_r[ni]);
        }
        if (++buf == 3) buf = 0;
    }

    int rbase = row0 + wm * 64 + (lane >> 2);
    int cbase = ncol0 + wn * 32 + (lane & 3) * 2;
#pragma unroll
    for (int mi = 0; mi < 4; mi++) {
#pragma unroll
        for (int ni = 0; ni < 4; ni++) {
            int gc = cbase + ni * 8;
            float b0 = __ldg(&bias[gc]), b1 = __ldg(&bias[gc + 1]);
#pragma unroll
            for (int half_ = 0; half_ < 2; half_++) {
                long gr = rbase + mi * 16 + half_ * 8;
                float v0 = c[mi][ni][half_ * 2 + 0] + b0;
                float v1 = c[mi][ni][half_ * 2 + 1] + b1;
                if (RELU) { v0 = fmaxf(v0, 0.f); v1 = fmaxf(v1, 0.f); }
                if (RESID) {
                    float2 rr = *(const float2*)&resid[gr * N + gc];
                    v0 += rr.x; v1 += rr.y;
                }
                if (WF32) {
                    float2 o; o.x = v0; o.y = v1;
                    *(float2*)&Cf[gr * N + gc] = o;
                }
                if (WH16) {
                    __half2 hh;
                    hh.x = __float2half_rn(v0); hh.y = __float2half_rn(v1);
                    *(__half2*)&Ch[gr * N + gc] = hh;
                }
            }
        }
    }
}

// ---------------------------------------------------------------------------
// HMMA flash attention (R15: K/V double-buffered).
// ---------------------------------------------------------------------------
#define FSTR 144   // smem row stride bytes (64 halves + 8 pad)
#define FQ_B (128 * FSTR)              // 18432
#define FKV_B (2 * 64 * FSTR)          // 18432 (K + V, one buffer)
#define FLASH_SMEM2 (FQ_B + 2 * FKV_B) // 55296

__global__ __launch_bounds__(256, 2)
void flash_attn_hmma(const __half* __restrict__ QKV, __half* __restrict__ Ao)
{
    extern __shared__ char sm8[];
    uint32_t sq = smem_u32(sm8);
    uint32_t skv0 = sq + FQ_B;

    int qt = gridDim.x - 1 - blockIdx.x;
    int bh = blockIdx.y;
    int b = bh >> 4, h = bh & 15;
    int tid = threadIdx.x, lane = tid & 31, wid = tid >> 5;

    const __half* Qg = QKV + (long)b * SEQ * QKVN + h * HDIM;
    const __half* Kg = Qg + 1024;
    const __half* Vg = Qg + 2048;

    for (int i = tid; i < 1024; i += 256) {
        int r = i >> 3, sg = i & 7;
        cp_async16(sq + (uint32_t)(r * FSTR + sg * 16),
                   Qg + (long)(qt * 128 + r) * QKVN + sg * 8);
    }
    cp_commit();

    auto load_kv = [&](int jt, int kbuf) {
        uint32_t sk = skv0 + kbuf * FKV_B;
        uint32_t sv = sk + 64 * FSTR;
        for (int i = tid; i < 512; i += 256) {
            int r = i >> 3, sg = i & 7;
            long g = (long)(jt * 64 + r) * QKVN + sg * 8;
            cp_async16(sk + (uint32_t)(r * FSTR + sg * 16), Kg + g);
            cp_async16(sv + (uint32_t)(r * FSTR + sg * 16), Vg + g);
        }
        cp_commit();
    };

    int arow = (lane & 7) + ((lane >> 3) & 1) * 8;
    int akk = ((lane >> 4) & 1) * 8;
    int bt = lane >> 3, br = lane & 7;
    int brow_off = (bt & 1) * 8 + br;
    int bcol_off = (bt >> 1) * 8;

    load_kv(0, 0);
    cp_wait<0>();
    __syncthreads();

    uint32_t a_q[4][4];
#pragma unroll
    for (int ks = 0; ks < 4; ks++)
        ldsm_x4(a_q[ks], sq + (uint32_t)((wid * 16 + arow) * FSTR + (ks * 16 + akk) * 2));

    float o[8][4];
#pragma unroll
    for (int i = 0; i < 8; i++)
#pragma unroll
        for (int j = 0; j < 4; j++) o[i][j] = 0.f;
    float m_[2] = {-1e30f, -1e30f}, l_[2] = {0.f, 0.f};

    int rloc = wid * 16 + (lane >> 2);
    int r0g = qt * 128 + rloc;
    int njt = 2 * qt + 2;

    for (int jt = 0; jt < njt; jt++) {
        int kbuf = jt & 1;
        if (jt > 0) {
            cp_wait<0>();
            __syncthreads();
        }
        if (jt + 1 < njt) load_kv(jt + 1, kbuf ^ 1);

        uint32_t sk = skv0 + kbuf * FKV_B;
        uint32_t sv = sk + 64 * FSTR;

        float cs[8][4];
#pragma unroll
        for (int i = 0; i < 8; i++)
#pragma unroll
            for (int j = 0; j < 4; j++) cs[i][j] = 0.f;

#pragma unroll
        for (int ks = 0; ks < 4; ks++) {
            uint32_t b_r[8][2];
#pragma unroll
            for (int p = 0; p < 4; p++) {
                uint32_t r[4];
                ldsm_x4(r, sk + (uint32_t)((p * 16 + arow) * FSTR + (ks * 16 + akk) * 2));
                b_r[2 * p][0] = r[0]; b_r[2 * p + 1][0] = r[1];
                b_r[2 * p][1] = r[2]; b_r[2 * p + 1][1] = r[3];
            }
#pragma unroll
            for (int ni = 0; ni < 8; ni++)
                mma_f16(cs[ni], a_q[ks], b_r[ni]);
        }

        bool need_mask = (jt * 64 + 63) > (qt * 128 + wid * 16);
        if (need_mask) {
#pragma unroll
            for (int ni = 0; ni < 8; ni++) {
                int k0c = jt * 64 + ni * 8 + (lane & 3) * 2;
#pragma unroll
                for (int hf = 0; hf < 2; hf++) {
                    int qrow = r0g + hf * 8;
                    float v0 = cs[ni][hf * 2 + 0] * 0.125f;
                    float v1 = cs[ni][hf * 2 + 1] * 0.125f;
                    cs[ni][hf * 2 + 0] = (k0c > qrow) ? -1e30f : v0;
                    cs[ni][hf * 2 + 1] = (k0c + 1 > qrow) ? -1e30f : v1;
                }
            }
        } else {
#pragma unroll
            for (int ni = 0; ni < 8; ni++)
#pragma unroll
                for (int j = 0; j < 4; j++) cs[ni][j] *= 0.125f;
        }

#pragma unroll
        for (int hf = 0; hf < 2; hf++) {
            float mx = m_[hf];
#pragma unroll
            for (int ni = 0; ni < 8; ni++)
                mx = fmaxf(mx, fmaxf(cs[ni][hf * 2], cs[ni][hf * 2 + 1]));
            mx = fmaxf(mx, __shfl_xor_sync(0xffffffffu, mx, 1));
            mx = fmaxf(mx, __shfl_xor_sync(0xffffffffu, mx, 2));
            float corr = __expf(m_[hf] - mx);
            float rsum = 0.f;
#pragma unroll
            for (int ni = 0; ni < 8; ni++) {
                float p0 = __expf(cs[ni][hf * 2 + 0] - mx);
                float p1 = __expf(cs[ni][hf * 2 + 1] - mx);
                cs[ni][hf * 2 + 0] = p0;
                cs[ni][hf * 2 + 1] = p1;
                rsum += p0 + p1;
            }
            rsum += __shfl_xor_sync(0xffffffffu, rsum, 1);
            rsum += __shfl_xor_sync(0xffffffffu, rsum, 2);
            l_[hf] = l_[hf] * corr + rsum;
            m_[hf] = mx;
#pragma unroll
            for (int ni = 0; ni < 8; ni++) {
                o[ni][hf * 2 + 0] *= corr;
                o[ni][hf * 2 + 1] *= corr;
            }
        }

#pragma unroll
        for (int ks2 = 0; ks2 < 4; ks2++) {
            uint32_t a_p[4];
            {
                __half2 t0 = __floats2half2_rn(cs[2 * ks2][0], cs[2 * ks2][1]);
                __half2 t1 = __floats2half2_rn(cs[2 * ks2][2], cs[2 * ks2][3]);
                __half2 t2 = __floats2half2_rn(cs[2 * ks2 + 1][0], cs[2 * ks2 + 1][1]);
                __half2 t3 = __floats2half2_rn(cs[2 * ks2 + 1][2], cs[2 * ks2 + 1][3]);
                a_p[0] = *(uint32_t*)&t0; a_p[1] = *(uint32_t*)&t1;
                a_p[2] = *(uint32_t*)&t2; a_p[3] = *(uint32_t*)&t3;
            }
            uint32_t b_v[8][2];
#pragma unroll
            for (int p = 0; p < 4; p++) {
                uint32_t r[4];
                ldsm_x4_trans(r, sv + (uint32_t)((ks2 * 16 + brow_off) * FSTR
                                                 + (p * 16 + bcol_off) * 2));
                b_v[2 * p][0] = r[0]; b_v[2 * p][1] = r[1];
                b_v[2 * p + 1][0] = r[2]; b_v[2 * p + 1][1] = r[3];
            }
#pragma unroll
            for (int ni = 0; ni < 8; ni++)
                mma_f16(o[ni], a_p, b_v[ni]);
        }
        __syncthreads();
    }

#pragma unroll
    for (int hf = 0; hf < 2; hf++) {
        float inv = 1.0f / l_[hf];
        long row = (long)(b * SEQ + r0g + hf * 8);
#pragma unroll
        for (int ni = 0; ni < 8; ni++) {
            __half2 hv = __floats2half2_rn(o[ni][hf * 2 + 0] * inv,
                                           o[ni][hf * 2 + 1] * inv);
            *(__half2*)&Ao[row * HK + h * HDIM + ni * 8 + (lane & 3) * 2] = hv;
        }
    }
}

// ---------------------------------------------------------------------------
// Launch: weight conversion forked onto a side stream, joined per-consumer.
// ---------------------------------------------------------------------------
extern "C" void kernel_launch(void* const* d_in, const int* in_sizes, int n_in,
                              void* d_out, int out_size)
{
    const int*   tokens = (const int*)  d_in[0];
    const float* emb    = (const float*)d_in[1];
    const float* pos    = (const float*)d_in[2];
    const float* Wq     = (const float*)d_in[3];
    const float* bq     = (const float*)d_in[4];
    const float* Wk     = (const float*)d_in[5];
    const float* bk     = (const float*)d_in[6];
    const float* Wv     = (const float*)d_in[7];
    const float* bv     = (const float*)d_in[8];
    const float* Wo     = (const float*)d_in[9];
    const float* bo     = (const float*)d_in[10];
    const float* W1     = (const float*)d_in[11];
    const float* b1     = (const float*)d_in[12];
    const float* W2     = (const float*)d_in[13];
    const float* b2     = (const float*)d_in[14];
    const float* Wf     = (const float*)d_in[15];
    const float* bf     = (const float*)d_in[16];
    float* out = (float*)d_out;

    float *x, *qkvb;
    __half *qkvh, *xh, *ah, *fh;
    __half *wqkv, *wo, *w1, *w2, *wf;
    cudaGetSymbolAddress((void**)&x, g_x);
    cudaGetSymbolAddress((void**)&qkvb, g_qkvb);
    cudaGetSymbolAddress((void**)&qkvh, g_qkvh);
    cudaGetSymbolAddress((void**)&xh, g_xh);
    cudaGetSymbolAddress((void**)&ah, g_ah);
    cudaGetSymbolAddress((void**)&fh, g_fh);
    cudaGetSymbolAddress((void**)&wqkv, g_wqkv);
    cudaGetSymbolAddress((void**)&wo, g_wo);
    cudaGetSymbolAddress((void**)&w1, g_w1);
    cudaGetSymbolAddress((void**)&w2, g_w2);
    cudaGetSymbolAddress((void**)&wf, g_wf);

    static cudaStream_t s2 = nullptr;
    static cudaEvent_t evFork = nullptr, evQKV = nullptr, evWo = nullptr,
                       evW1 = nullptr, evW2 = nullptr, evWf = nullptr;
    static bool init_done = false;
    if (!init_done) {
        cudaFuncSetAttribute(flash_attn_hmma,
                             cudaFuncAttributeMaxDynamicSharedMemorySize, FLASH_SMEM2);
        cudaFuncSetAttribute(hmma_gemm<false, false, true, false>,
                             cudaFuncAttributeMaxDynamicSharedMemorySize, GEMM_SMEM);
        cudaFuncSetAttribute(hmma_gemm<false, false, false, true>,
                             cudaFuncAttributeMaxDynamicSharedMemorySize, GEMM_SMEM);
        cudaFuncSetAttribute(hmma_gemm<false, true, true, true>,
                             cudaFuncAttributeMaxDynamicSharedMemorySize, GEMM_SMEM);
        cudaFuncSetAttribute(hmma_gemm<true, false, false, true>,
                             cudaFuncAttributeMaxDynamicSharedMemorySize, GEMM_SMEM);
        cudaStreamCreateWithFlags(&s2, cudaStreamNonBlocking);
        cudaEventCreateWithFlags(&evFork, cudaEventDisableTiming);
        cudaEventCreateWithFlags(&evQKV, cudaEventDisableTiming);
        cudaEventCreateWithFlags(&evWo, cudaEventDisableTiming);
        cudaEventCreateWithFlags(&evW1, cudaEventDisableTiming);
        cudaEventCreateWithFlags(&evW2, cudaEventDisableTiming);
        cudaEventCreateWithFlags(&evWf, cudaEventDisableTiming);
        init_done = true;
    }

    // ---- fork: weight conversions on side stream ----
    cudaEventRecord(evFork, 0);
    cudaStreamWaitEvent(s2, evFork, 0);

    wconv_qkv<<<NLAYER * DMODEL, 64, 0, s2>>>(Wq, wqkv, 0);
    wconv_qkv<<<NLAYER * DMODEL, 64, 0, s2>>>(Wk, wqkv, 1024);
    wconv_qkv<<<NLAYER * DMODEL, 64, 0, s2>>>(Wv, wqkv, 2048);
    cudaEventRecord(evQKV, s2);
    {
        long n16 = (long)NLAYER * HK * DMODEL / 16;
        wconv_flat<<<(unsigned)((n16 + 255) / 256), 256, 0, s2>>>(Wo, wo, n16);
        cudaEventRecord(evWo, s2);
        n16 = (long)NLAYER * DMODEL * FFDIM / 16;
        wconv_flat<<<(unsigned)((n16 + 255) / 256), 256, 0, s2>>>(W1, w1, n16);
        cudaEventRecord(evW1, s2);
        wconv_flat<<<(unsigned)((n16 + 255) / 256), 256, 0, s2>>>(W2, w2, n16);
        cudaEventRecord(evW2, s2);
        n16 = (long)DMODEL * VOCAB / 16;
        wconv_flat<<<(unsigned)((n16 + 255) / 256), 256, 0, s2>>>(Wf, wf, n16);
        cudaEventRecord(evWf, s2);
    }

    // ---- main stream: embed + bias while conversions stream ----
    bias_concat_kernel<<<(NLAYER * QKVN + 255) / 256, 256>>>(bq, bk, bv, qkvb);
    embed_kernel<<<MTOK, 256>>>(tokens, emb, pos, x, xh);

    dim3 gQKV(MTOK / 128, QKVN / 128);
    dim3 gProj(MTOK / 128, DMODEL / 128);
    dim3 gFF1(MTOK / 128, FFDIM / 128);
    dim3 gLogits(MTOK / 128, VOCAB / 128);
    dim3 gAttn(SEQ / 128, BATCH * NHEAD);   // 16 x 32

    for (int l = 0; l < NLAYER; l++) {
        if (l == 0) cudaStreamWaitEvent(0, evQKV, 0);
        // qkv = x @ Wqkv + b  (fp16 out)
        hmma_gemm<false, false, false, true><<<gQKV, 256, GEMM_SMEM>>>(
            xh, wqkv + (long)l * DMODEL * QKVN, qkvb + (long)l * QKVN, nullptr,
            nullptr, qkvh, QKVN, DMODEL);

        flash_attn_hmma<<<gAttn, 256, FLASH_SMEM2>>>(qkvh, ah);

        if (l == 0) cudaStreamWaitEvent(0, evWo, 0);
        // x = x + a @ Wo + bo  (fp32 + fp16 out)
        hmma_gemm<false, true, true, true><<<gProj, 256, GEMM_SMEM>>>(
            ah, wo + (long)l * HK * DMODEL,
            bo + (long)l * DMODEL, x, x, xh, DMODEL, HK);

        if (l == 0) cudaStreamWaitEvent(0, evW1, 0);
        // f = relu(x @ W1 + b1)  (fp16 only)
        hmma_gemm<true, false, false, true><<<gFF1, 256, GEMM_SMEM>>>(
            xh, w1 + (long)l * DMODEL * FFDIM,
            b1 + (long)l * FFDIM, nullptr, nullptr, fh, FFDIM, DMODEL);

        if (l == 0) cudaStreamWaitEvent(0, evW2, 0);
        // x = x + f @ W2 + b2
        hmma_gemm<false, true, true, true><<<gProj, 256, GEMM_SMEM>>>(
            fh, w2 + (long)l * FFDIM * DMODEL,
            b2 + (long)l * DMODEL, x, x, xh, DMODEL, FFDIM);
    }

    // logits = x @ Wf + bf
    cudaStreamWaitEvent(0, evWf, 0);
    hmma_gemm<false, false, true, false><<<gLogits, 256, GEMM_SMEM>>>(
        xh, wf, bf, nullptr, out, nullptr, VOCAB, DMODEL);
}

// round 17
// speedup vs baseline: 1.3619x; 1.0446x over previous
#include <cuda_runtime.h>
#include <cuda_fp16.h>
#include <cstdint>

// Problem constants
#define VOCAB 32000
#define DMODEL 1024
#define NHEAD 16
#define HDIM 64
#define FFDIM 4096
#define NLAYER 4
#define SEQ 2048
#define BATCH 2
#define MTOK (BATCH * SEQ)      // 4096 token rows
#define HK (NHEAD * HDIM)       // 1024
#define QKVN 3072               // fused q|k|v output width

// ---------------------------------------------------------------------------
// Scratch (device globals; no allocations allowed)
// ---------------------------------------------------------------------------
__device__ float g_x[MTOK * DMODEL];                 // residual stream fp32
__device__ float g_qkvb[NLAYER * QKVN];              // fused qkv bias
__device__ __half g_qkvh[MTOK * QKVN];               // fused qkv fp16
__device__ __half g_xh[MTOK * DMODEL];               // activations fp16
__device__ __half g_ah[MTOK * HK];
__device__ __half g_fh[MTOK * FFDIM];
// fp16 weights, NATURAL [K,N] layout
__device__ __half g_wqkv[NLAYER * DMODEL * QKVN];
__device__ __half g_wo[NLAYER * HK * DMODEL];
__device__ __half g_w1[NLAYER * DMODEL * FFDIM];
__device__ __half g_w2[NLAYER * FFDIM * DMODEL];
__device__ __half g_wf[DMODEL * VOCAB];

// ---------------------------------------------------------------------------
// PTX helpers (all sm_80-era, arch-portable)
// ---------------------------------------------------------------------------
__device__ __forceinline__ uint32_t smem_u32(const void* p) {
    return (uint32_t)__cvta_generic_to_shared(p);
}
__device__ __forceinline__ void cp_async16(uint32_t dst, const void* src) {
    asm volatile("cp.async.cg.shared.global [%0], [%1], 16;\n" :: "r"(dst), "l"(src));
}
__device__ __forceinline__ void cp_commit() { asm volatile("cp.async.commit_group;\n" ::: "memory"); }
template<int N> __device__ __forceinline__ void cp_wait() {
    asm volatile("cp.async.wait_group %0;\n" :: "n"(N) : "memory");
}
__device__ __forceinline__ void ldsm_x4(uint32_t* r, uint32_t addr) {
    asm volatile("ldmatrix.sync.aligned.m8n8.x4.shared.b16 {%0,%1,%2,%3}, [%4];"
                 : "=r"(r[0]), "=r"(r[1]), "=r"(r[2]), "=r"(r[3]) : "r"(addr));
}
__device__ __forceinline__ void ldsm_x4_trans(uint32_t* r, uint32_t addr) {
    asm volatile("ldmatrix.sync.aligned.m8n8.x4.trans.shared.b16 {%0,%1,%2,%3}, [%4];"
                 : "=r"(r[0]), "=r"(r[1]), "=r"(r[2]), "=r"(r[3]) : "r"(addr));
}
__device__ __forceinline__ void mma_f16(float* c, const uint32_t* a, const uint32_t* b) {
    asm volatile(
        "mma.sync.aligned.m16n8k16.row.col.f32.f16.f16.f32 "
        "{%0,%1,%2,%3}, {%4,%5,%6,%7}, {%8,%9}, {%0,%1,%2,%3};"
        : "+f"(c[0]), "+f"(c[1]), "+f"(c[2]), "+f"(c[3])
        : "r"(a[0]), "r"(a[1]), "r"(a[2]), "r"(a[3]), "r"(b[0]), "r"(b[1]));
}

// ---------------------------------------------------------------------------
// Flat weight convert: fp32 -> fp16, 16 elements per thread (2x 16B stores).
// ---------------------------------------------------------------------------
__global__ void wconv_flat(const float* __restrict__ W, __half* __restrict__ Wh,
                           long n16)
{
    long i = (long)blockIdx.x * blockDim.x + threadIdx.x;
    if (i >= n16) return;
    const float4* p = (const float4*)(W + i * 16);
    float4 a = p[0], b = p[1], cc = p[2], d = p[3];
    __half2 h0 = __floats2half2_rn(a.x, a.y), h1 = __floats2half2_rn(a.z, a.w);
    __half2 h2 = __floats2half2_rn(b.x, b.y), h3 = __floats2half2_rn(b.z, b.w);
    __half2 h4 = __floats2half2_rn(cc.x, cc.y), h5 = __floats2half2_rn(cc.z, cc.w);
    __half2 h6 = __floats2half2_rn(d.x, d.y), h7 = __floats2half2_rn(d.z, d.w);
    uint4 o0, o1;
    o0.x = *(uint32_t*)&h0; o0.y = *(uint32_t*)&h1;
    o0.z = *(uint32_t*)&h2; o0.w = *(uint32_t*)&h3;
    o1.x = *(uint32_t*)&h4; o1.y = *(uint32_t*)&h5;
    o1.z = *(uint32_t*)&h6; o1.w = *(uint32_t*)&h7;
    uint4* q = (uint4*)(Wh + i * 16);
    q[0] = o0; q[1] = o1;
}

// Packed qkv convert, all three tensors in one launch (blockIdx.y = 0:q 1:k 2:v).
__global__ void wconv_qkv3(const float* __restrict__ Wq, const float* __restrict__ Wk,
                           const float* __restrict__ Wv, __half* __restrict__ Wh)
{
    long row = blockIdx.x;
    int sel = blockIdx.y;
    const float* W = (sel == 0) ? Wq : (sel == 1) ? Wk : Wv;
    int t = threadIdx.x;               // 0..63
    const float4* p = (const float4*)(W + row * HK + t * 16);
    float4 a = p[0], b = p[1], cc = p[2], d = p[3];
    __half2 h0 = __floats2half2_rn(a.x, a.y), h1 = __floats2half2_rn(a.z, a.w);
    __half2 h2 = __floats2half2_rn(b.x, b.y), h3 = __floats2half2_rn(b.z, b.w);
    __half2 h4 = __floats2half2_rn(cc.x, cc.y), h5 = __floats2half2_rn(cc.z, cc.w);
    __half2 h6 = __floats2half2_rn(d.x, d.y), h7 = __floats2half2_rn(d.z, d.w);
    uint4 o0, o1;
    o0.x = *(uint32_t*)&h0; o0.y = *(uint32_t*)&h1;
    o0.z = *(uint32_t*)&h2; o0.w = *(uint32_t*)&h3;
    o1.x = *(uint32_t*)&h4; o1.y = *(uint32_t*)&h5;
    o1.z = *(uint32_t*)&h6; o1.w = *(uint32_t*)&h7;
    uint4* q = (uint4*)(Wh + row * QKVN + sel * 1024 + t * 16);
    q[0] = o0; q[1] = o1;
}

// ---------------------------------------------------------------------------
// Embedding: x = emb[token] + pos ; also writes fp16
// ---------------------------------------------------------------------------
__global__ void embed_kernel(const int* __restrict__ tokens,
                             const float* __restrict__ emb,
                             const float* __restrict__ pos,
                             float* __restrict__ x,
                             __half* __restrict__ xh)
{
    int row = blockIdx.x;
    int s = row & (SEQ - 1);
    int t = tokens[row];
    const float4* e = (const float4*)(emb + (long)t * DMODEL);
    const float4* p = (const float4*)(pos + (long)s * DMODEL);
    for (int d = threadIdx.x; d < DMODEL / 4; d += blockDim.x) {
        float4 a = e[d], b = p[d];
        a.x += b.x; a.y += b.y; a.z += b.z; a.w += b.w;
        long o = (long)row * DMODEL + d * 4;
        *(float4*)&x[o] = a;
        __half2 h01, h23;
        h01.x = __float2half_rn(a.x); h01.y = __float2half_rn(a.y);
        h23.x = __float2half_rn(a.z); h23.y = __float2half_rn(a.w);
        *(__half2*)&xh[o] = h01; *(__half2*)&xh[o + 2] = h23;
    }
}

// qkv bias concat
__global__ void bias_concat_kernel(const float* __restrict__ bq, const float* __restrict__ bk,
                                   const float* __restrict__ bv, float* __restrict__ out)
{
    int i = blockIdx.x * blockDim.x + threadIdx.x;
    if (i >= NLAYER * QKVN) return;
    int l = i / QKVN, c = i - l * QKVN;
    float v = (c < 1024) ? bq[l * 1024 + c]
            : (c < 2048) ? bk[l * 1024 + c - 1024]
                         : bv[l * 1024 + c - 2048];
    out[i] = v;
}

// ---------------------------------------------------------------------------
// HMMA GEMM: C[M,N] = A[M,K] @ B  (A fp16 [M,K]; B fp16 [K,N] natural)
// CTA 128x128, BK=64, 8 warps (2x4), warp tile 64x32, mma.sync m16n8k16.
// fp32 accumulation; 3-stage cp.async pipeline; 2 CTAs/SM.
// ---------------------------------------------------------------------------
#define ASTRIDE 144                 // A smem row stride bytes (64 halves + pad)
#define ATILE_B 18432               // [128][72] halves
#define BSTRIDE 272                 // B smem row stride bytes (128 halves + pad)
#define BTILE_B 17408               // [64][136] halves
#define STAGE_B (ATILE_B + BTILE_B)       // 35840
#define GEMM_SMEM (3 * STAGE_B)           // 107520

template<bool RELU, bool RESID, bool WF32, bool WH16>
__global__ __launch_bounds__(256, 2)
void hmma_gemm(const __half* __restrict__ A, const __half* __restrict__ B,
               const float* __restrict__ bias, const float* __restrict__ resid,
               float* __restrict__ Cf, __half* __restrict__ Ch,
               int N, int K)
{
    extern __shared__ char smem[];
    uint32_t sbase = smem_u32(smem);

    int tid = threadIdx.x;
    int lane = tid & 31;
    int wid = tid >> 5;
    int wm = wid & 1;
    int wn = wid >> 1;
    int row0 = blockIdx.x * 128;
    int ncol0 = blockIdx.y * 128;
    int nk = K >> 6;

    float c[4][4][4];
#pragma unroll
    for (int i = 0; i < 4; i++)
#pragma unroll
        for (int j = 0; j < 4; j++)
#pragma unroll
            for (int k = 0; k < 4; k++) c[i][j][k] = 0.f;

    auto load_stage = [&](int chunk, int buf) {
        uint32_t sb = sbase + buf * STAGE_B;
        int kc = chunk << 6;
#pragma unroll 4
        for (int i = tid; i < 1024; i += 256) {
            int r = i >> 3, sg = i & 7;
            cp_async16(sb + (uint32_t)(r * ASTRIDE + sg * 16),
                       A + (long)(row0 + r) * K + kc + sg * 8);
        }
#pragma unroll 4
        for (int i = tid; i < 1024; i += 256) {
            int r = i >> 4, cc = i & 15;
            cp_async16(sb + ATILE_B + (uint32_t)(r * BSTRIDE + cc * 16),
                       B + (long)(kc + r) * N + ncol0 + cc * 8);
        }
        cp_commit();
    };

    load_stage(0, 0);
    load_stage(1, 1);

    int arow = (lane & 7) + ((lane >> 3) & 1) * 8;
    int akk = ((lane >> 4) & 1) * 8;
    int bt = lane >> 3, br = lane & 7;
    int brow_off = (bt & 1) * 8 + br;
    int bcol_off = (bt >> 1) * 8;

    int buf = 0;
    for (int ch = 0; ch < nk; ch++) {
        if (ch + 1 < nk) cp_wait<1>(); else cp_wait<0>();
        __syncthreads();
        if (ch + 2 < nk) {
            int nb = buf + 2; if (nb >= 3) nb -= 3;
            load_stage(ch + 2, nb);
        }

        uint32_t sb = sbase + buf * STAGE_B;
#pragma unroll
        for (int ks = 0; ks < 4; ks++) {
            int k0 = ks * 16;
            uint32_t a_r[4][4], b_r[4][2];
#pragma unroll
            for (int mi = 0; mi < 4; mi++) {
                uint32_t ad = sb + (uint32_t)((wm * 64 + mi * 16 + arow) * ASTRIDE
                                              + (k0 + akk) * 2);
                ldsm_x4(a_r[mi], ad);
            }
#pragma unroll
            for (int p = 0; p < 2; p++) {
                uint32_t bd = sb + ATILE_B
                            + (uint32_t)((k0 + brow_off) * BSTRIDE
                                         + (wn * 32 + p * 16 + bcol_off) * 2);
                uint32_t r[4];
                ldsm_x4_trans(r, bd);
                b_r[2 * p][0] = r[0]; b_r[2 * p][1] = r[1];
                b_r[2 * p + 1][0] = r[2]; b_r[2 * p + 1][1] = r[3];
            }
#pragma unroll
            for (int mi = 0; mi < 4; mi++)
#pragma unroll
                for (int ni = 0; ni < 4; ni++)
                    mma_f16(c[mi][ni], a_r[mi], b_r[ni]);
        }
        if (++buf == 3) buf = 0;
    }

    int rbase = row0 + wm * 64 + (lane >> 2);
    int cbase = ncol0 + wn * 32 + (lane & 3) * 2;
#pragma unroll
    for (int mi = 0; mi < 4; mi++) {
#pragma unroll
        for (int ni = 0; ni < 4; ni++) {
            int gc = cbase + ni * 8;
            float b0 = __ldg(&bias[gc]), b1 = __ldg(&bias[gc + 1]);
#pragma unroll
            for (int half_ = 0; half_ < 2; half_++) {
                long gr = rbase + mi * 16 + half_ * 8;
                float v0 = c[mi][ni][half_ * 2 + 0] + b0;
                float v1 = c[mi][ni][half_ * 2 + 1] + b1;
                if (RELU) { v0 = fmaxf(v0, 0.f); v1 = fmaxf(v1, 0.f); }
                if (RESID) {
                    float2 rr = *(const float2*)&resid[gr * N + gc];
                    v0 += rr.x; v1 += rr.y;
                }
                if (WF32) {
                    float2 o; o.x = v0; o.y = v1;
                    *(float2*)&Cf[gr * N + gc] = o;
                }
                if (WH16) {
                    __half2 hh;
                    hh.x = __float2half_rn(v0); hh.y = __float2half_rn(v1);
                    *(__half2*)&Ch[gr * N + gc] = hh;
                }
            }
        }
    }
}

// ---------------------------------------------------------------------------
// HMMA flash attention. 1-D grid, globally heavy-first (LPT) tile order.
// K/V double-buffered; single barrier per tile iteration.
// ---------------------------------------------------------------------------
#define FSTR 144   // smem row stride bytes (64 halves + 8 pad)
#define FQ_B (128 * FSTR)              // 18432
#define FKV_B (2 * 64 * FSTR)          // 18432 (K + V, one buffer)
#define FLASH_SMEM2 (FQ_B + 2 * FKV_B) // 55296

__global__ __launch_bounds__(256, 2)
void flash_attn_hmma(const __half* __restrict__ QKV, __half* __restrict__ Ao)
{
    extern __shared__ char sm8[];
    uint32_t sq = smem_u32(sm8);
    uint32_t skv0 = sq + FQ_B;

    // Global LPT order: all heads' heaviest q-tiles first.
    int flat = blockIdx.x;                     // 0..511
    int qt = (SEQ / 128 - 1) - (flat >> 5);    // 15,15,...(32x),14,...
    int bh = flat & 31;
    int b = bh >> 4, h = bh & 15;
    int tid = threadIdx.x, lane = tid & 31, wid = tid >> 5;

    const __half* Qg = QKV + (long)b * SEQ * QKVN + h * HDIM;
    const __half* Kg = Qg + 1024;
    const __half* Vg = Qg + 2048;

    for (int i = tid; i < 1024; i += 256) {
        int r = i >> 3, sg = i & 7;
        cp_async16(sq + (uint32_t)(r * FSTR + sg * 16),
                   Qg + (long)(qt * 128 + r) * QKVN + sg * 8);
    }
    cp_commit();

    auto load_kv = [&](int jt, int kbuf) {
        uint32_t sk = skv0 + kbuf * FKV_B;
        uint32_t sv = sk + 64 * FSTR;
        for (int i = tid; i < 512; i += 256) {
            int r = i >> 3, sg = i & 7;
            long g = (long)(jt * 64 + r) * QKVN + sg * 8;
            cp_async16(sk + (uint32_t)(r * FSTR + sg * 16), Kg + g);
            cp_async16(sv + (uint32_t)(r * FSTR + sg * 16), Vg + g);
        }
        cp_commit();
    };

    int arow = (lane & 7) + ((lane >> 3) & 1) * 8;
    int akk = ((lane >> 4) & 1) * 8;
    int bt = lane >> 3, br = lane & 7;
    int brow_off = (bt & 1) * 8 + br;
    int bcol_off = (bt >> 1) * 8;

    load_kv(0, 0);
    cp_wait<0>();
    __syncthreads();

    uint32_t a_q[4][4];
#pragma unroll
    for (int ks = 0; ks < 4; ks++)
        ldsm_x4(a_q[ks], sq + (uint32_t)((wid * 16 + arow) * FSTR + (ks * 16 + akk) * 2));

    float o[8][4];
#pragma unroll
    for (int i = 0; i < 8; i++)
#pragma unroll
        for (int j = 0; j < 4; j++) o[i][j] = 0.f;
    float m_[2] = {-1e30f, -1e30f}, l_[2] = {0.f, 0.f};

    int rloc = wid * 16 + (lane >> 2);
    int r0g = qt * 128 + rloc;
    int njt = 2 * qt + 2;

    for (int jt = 0; jt < njt; jt++) {
        int kbuf = jt & 1;
        if (jt > 0) {
            cp_wait<0>();
            __syncthreads();   // orders: prefetch done + all warps done with prev buffer
        }
        if (jt + 1 < njt) load_kv(jt + 1, kbuf ^ 1);

        uint32_t sk = skv0 + kbuf * FKV_B;
        uint32_t sv = sk + 64 * FSTR;

        float cs[8][4];
#pragma unroll
        for (int i = 0; i < 8; i++)
#pragma unroll
            for (int j = 0; j < 4; j++) cs[i][j] = 0.f;

#pragma unroll
        for (int ks = 0; ks < 4; ks++) {
            uint32_t b_r[8][2];
#pragma unroll
            for (int p = 0; p < 4; p++) {
                uint32_t r[4];
                ldsm_x4(r, sk + (uint32_t)((p * 16 + arow) * FSTR + (ks * 16 + akk) * 2));
                b_r[2 * p][0] = r[0]; b_r[2 * p + 1][0] = r[1];
                b_r[2 * p][1] = r[2]; b_r[2 * p + 1][1] = r[3];
            }
#pragma unroll
            for (int ni = 0; ni < 8; ni++)
                mma_f16(cs[ni], a_q[ks], b_r[ni]);
        }

        bool need_mask = (jt * 64 + 63) > (qt * 128 + wid * 16);
        if (need_mask) {
#pragma unroll
            for (int ni = 0; ni < 8; ni++) {
                int k0c = jt * 64 + ni * 8 + (lane & 3) * 2;
#pragma unroll
                for (int hf = 0; hf < 2; hf++) {
                    int qrow = r0g + hf * 8;
                    float v0 = cs[ni][hf * 2 + 0] * 0.125f;
                    float v1 = cs[ni][hf * 2 + 1] * 0.125f;
                    cs[ni][hf * 2 + 0] = (k0c > qrow) ? -1e30f : v0;
                    cs[ni][hf * 2 + 1] = (k0c + 1 > qrow) ? -1e30f : v1;
                }
            }
        } else {
#pragma unroll
            for (int ni = 0; ni < 8; ni++)
#pragma unroll
                for (int j = 0; j < 4; j++) cs[ni][j] *= 0.125f;
        }

#pragma unroll
        for (int hf = 0; hf < 2; hf++) {
            float mx = m_[hf];
#pragma unroll
            for (int ni = 0; ni < 8; ni++)
                mx = fmaxf(mx, fmaxf(cs[ni][hf * 2], cs[ni][hf * 2 + 1]));
            mx = fmaxf(mx, __shfl_xor_sync(0xffffffffu, mx, 1));
            mx = fmaxf(mx, __shfl_xor_sync(0xffffffffu, mx, 2));
            float corr = __expf(m_[hf] - mx);
            float rsum = 0.f;
#pragma unroll
            for (int ni = 0; ni < 8; ni++) {
                float p0 = __expf(cs[ni][hf * 2 + 0] - mx);
                float p1 = __expf(cs[ni][hf * 2 + 1] - mx);
                cs[ni][hf * 2 + 0] = p0;
                cs[ni][hf * 2 + 1] = p1;
                rsum += p0 + p1;
            }
            rsum += __shfl_xor_sync(0xffffffffu, rsum, 1);
            rsum += __shfl_xor_sync(0xffffffffu, rsum, 2);
            l_[hf] = l_[hf] * corr + rsum;
            m_[hf] = mx;
#pragma unroll
            for (int ni = 0; ni < 8; ni++) {
                o[ni][hf * 2 + 0] *= corr;
                o[ni][hf * 2 + 1] *= corr;
            }
        }

#pragma unroll
        for (int ks2 = 0; ks2 < 4; ks2++) {
            uint32_t a_p[4];
            {
                __half2 t0 = __floats2half2_rn(cs[2 * ks2][0], cs[2 * ks2][1]);
                __half2 t1 = __floats2half2_rn(cs[2 * ks2][2], cs[2 * ks2][3]);
                __half2 t2 = __floats2half2_rn(cs[2 * ks2 + 1][0], cs[2 * ks2 + 1][1]);
                __half2 t3 = __floats2half2_rn(cs[2 * ks2 + 1][2], cs[2 * ks2 + 1][3]);
                a_p[0] = *(uint32_t*)&t0; a_p[1] = *(uint32_t*)&t1;
                a_p[2] = *(uint32_t*)&t2; a_p[3] = *(uint32_t*)&t3;
            }
            uint32_t b_v[8][2];
#pragma unroll
            for (int p = 0; p < 4; p++) {
                uint32_t r[4];
                ldsm_x4_trans(r, sv + (uint32_t)((ks2 * 16 + brow_off) * FSTR
                                                 + (p * 16 + bcol_off) * 2));
                b_v[2 * p][0] = r[0]; b_v[2 * p][1] = r[1];
                b_v[2 * p + 1][0] = r[2]; b_v[2 * p + 1][1] = r[3];
            }
#pragma unroll
            for (int ni = 0; ni < 8; ni++)
                mma_f16(o[ni], a_p, b_v[ni]);
        }
        // no trailing barrier: next iteration's post-wait __syncthreads orders
        // all reads of this buffer before any overwrite (prefetch jt+2).
    }

#pragma unroll
    for (int hf = 0; hf < 2; hf++) {
        float inv = 1.0f / l_[hf];
        long row = (long)(b * SEQ + r0g + hf * 8);
#pragma unroll
        for (int ni = 0; ni < 8; ni++) {
            __half2 hv = __floats2half2_rn(o[ni][hf * 2 + 0] * inv,
                                           o[ni][hf * 2 + 1] * inv);
            *(__half2*)&Ao[row * HK + h * HDIM + ni * 8 + (lane & 3) * 2] = hv;
        }
    }
}

// ---------------------------------------------------------------------------
// Launch: weight conversion forked onto a side stream, joined per-consumer.
// ---------------------------------------------------------------------------
extern "C" void kernel_launch(void* const* d_in, const int* in_sizes, int n_in,
                              void* d_out, int out_size)
{
    const int*   tokens = (const int*)  d_in[0];
    const float* emb    = (const float*)d_in[1];
    const float* pos    = (const float*)d_in[2];
    const float* Wq     = (const float*)d_in[3];
    const float* bq     = (const float*)d_in[4];
    const float* Wk     = (const float*)d_in[5];
    const float* bk     = (const float*)d_in[6];
    const float* Wv     = (const float*)d_in[7];
    const float* bv     = (const float*)d_in[8];
    const float* Wo     = (const float*)d_in[9];
    const float* bo     = (const float*)d_in[10];
    const float* W1     = (const float*)d_in[11];
    const float* b1     = (const float*)d_in[12];
    const float* W2     = (const float*)d_in[13];
    const float* b2     = (const float*)d_in[14];
    const float* Wf     = (const float*)d_in[15];
    const float* bf     = (const float*)d_in[16];
    float* out = (float*)d_out;

    float *x, *qkvb;
    __half *qkvh, *xh, *ah, *fh;
    __half *wqkv, *wo, *w1, *w2, *wf;
    cudaGetSymbolAddress((void**)&x, g_x);
    cudaGetSymbolAddress((void**)&qkvb, g_qkvb);
    cudaGetSymbolAddress((void**)&qkvh, g_qkvh);
    cudaGetSymbolAddress((void**)&xh, g_xh);
    cudaGetSymbolAddress((void**)&ah, g_ah);
    cudaGetSymbolAddress((void**)&fh, g_fh);
    cudaGetSymbolAddress((void**)&wqkv, g_wqkv);
    cudaGetSymbolAddress((void**)&wo, g_wo);
    cudaGetSymbolAddress((void**)&w1, g_w1);
    cudaGetSymbolAddress((void**)&w2, g_w2);
    cudaGetSymbolAddress((void**)&wf, g_wf);

    static cudaStream_t s2 = nullptr;
    static cudaEvent_t evFork = nullptr, evQKV = nullptr, evWo = nullptr,
                       evW1 = nullptr, evW2 = nullptr, evWf = nullptr;
    static bool init_done = false;
    if (!init_done) {
        cudaFuncSetAttribute(flash_attn_hmma,
                             cudaFuncAttributeMaxDynamicSharedMemorySize, FLASH_SMEM2);
        cudaFuncSetAttribute(hmma_gemm<false, false, true, false>,
                             cudaFuncAttributeMaxDynamicSharedMemorySize, GEMM_SMEM);
        cudaFuncSetAttribute(hmma_gemm<false, false, false, true>,
                             cudaFuncAttributeMaxDynamicSharedMemorySize, GEMM_SMEM);
        cudaFuncSetAttribute(hmma_gemm<false, true, true, true>,
                             cudaFuncAttributeMaxDynamicSharedMemorySize, GEMM_SMEM);
        cudaFuncSetAttribute(hmma_gemm<true, false, false, true>,
                             cudaFuncAttributeMaxDynamicSharedMemorySize, GEMM_SMEM);
        cudaStreamCreateWithFlags(&s2, cudaStreamNonBlocking);
        cudaEventCreateWithFlags(&evFork, cudaEventDisableTiming);
        cudaEventCreateWithFlags(&evQKV, cudaEventDisableTiming);
        cudaEventCreateWithFlags(&evWo, cudaEventDisableTiming);
        cudaEventCreateWithFlags(&evW1, cudaEventDisableTiming);
        cudaEventCreateWithFlags(&evW2, cudaEventDisableTiming);
        cudaEventCreateWithFlags(&evWf, cudaEventDisableTiming);
        init_done = true;
    }

    // ---- fork: weight conversions on side stream ----
    cudaEventRecord(evFork, 0);
    cudaStreamWaitEvent(s2, evFork, 0);

    wconv_qkv3<<<dim3(NLAYER * DMODEL, 3), 64, 0, s2>>>(Wq, Wk, Wv, wqkv);
    cudaEventRecord(evQKV, s2);
    {
        long n16 = (long)NLAYER * HK * DMODEL / 16;
        wconv_flat<<<(unsigned)((n16 + 255) / 256), 256, 0, s2>>>(Wo, wo, n16);
        cudaEventRecord(evWo, s2);
        n16 = (long)NLAYER * DMODEL * FFDIM / 16;
        wconv_flat<<<(unsigned)((n16 + 255) / 256), 256, 0, s2>>>(W1, w1, n16);
        cudaEventRecord(evW1, s2);
        wconv_flat<<<(unsigned)((n16 + 255) / 256), 256, 0, s2>>>(W2, w2, n16);
        cudaEventRecord(evW2, s2);
        n16 = (long)DMODEL * VOCAB / 16;
        wconv_flat<<<(unsigned)((n16 + 255) / 256), 256, 0, s2>>>(Wf, wf, n16);
        cudaEventRecord(evWf, s2);
    }

    // ---- main stream: embed + bias while conversions stream ----
    bias_concat_kernel<<<(NLAYER * QKVN + 255) / 256, 256>>>(bq, bk, bv, qkvb);
    embed_kernel<<<MTOK, 256>>>(tokens, emb, pos, x, xh);

    dim3 gQKV(MTOK / 128, QKVN / 128);
    dim3 gProj(MTOK / 128, DMODEL / 128);
    dim3 gFF1(MTOK / 128, FFDIM / 128);
    dim3 gLogits(MTOK / 128, VOCAB / 128);

    for (int l = 0; l < NLAYER; l++) {
        if (l == 0) cudaStreamWaitEvent(0, evQKV, 0);
        // qkv = x @ Wqkv + b  (fp16 out)
        hmma_gemm<false, false, false, true><<<gQKV, 256, GEMM_SMEM>>>(
            xh, wqkv + (long)l * DMODEL * QKVN, qkvb + (long)l * QKVN, nullptr,
            nullptr, qkvh, QKVN, DMODEL);

        flash_attn_hmma<<<(SEQ / 128) * 32, 256, FLASH_SMEM2>>>(qkvh, ah);

        if (l == 0) cudaStreamWaitEvent(0, evWo, 0);
        // x = x + a @ Wo + bo  (fp32 + fp16 out)
        hmma_gemm<false, true, true, true><<<gProj, 256, GEMM_SMEM>>>(
            ah, wo + (long)l * HK * DMODEL,
            bo + (long)l * DMODEL, x, x, xh, DMODEL, HK);

        if (l == 0) cudaStreamWaitEvent(0, evW1, 0);
        // f = relu(x @ W1 + b1)  (fp16 only)
        hmma_gemm<true, false, false, true><<<gFF1, 256, GEMM_SMEM>>>(
            xh, w1 + (long)l * DMODEL * FFDIM,
            b1 + (long)l * FFDIM, nullptr, nullptr, fh, FFDIM, DMODEL);

        if (l == 0) cudaStreamWaitEvent(0, evW2, 0);
        // x = x + f @ W2 + b2
        hmma_gemm<false, true, true, true><<<gProj, 256, GEMM_SMEM>>>(
            fh, w2 + (long)l * FFDIM * DMODEL,
            b2 + (long)l * DMODEL, x, x, xh, DMODEL, FFDIM);
    }

    // logits = x @ Wf + bf
    cudaStreamWaitEvent(0, evWf, 0);
    hmma_gemm<false, false, true, false><<<gLogits, 256, GEMM_SMEM>>>(
        xh, wf, bf, nullptr, out, nullptr, VOCAB, DMODEL);
}